// round 1
// baseline (speedup 1.0000x reference)
#include <cuda_runtime.h>
#include <cstdint>

typedef unsigned long long ull;

// ---------------- static scratch (no allocations allowed) ----------------
__device__ float g_Wf[4][80][64];          // folded weights: [stage][o<8:q,8..15:k,16..79:v][c]
__device__ float g_bf[4][80];              // folded biases
__device__ float g_q[4][8 * 8192];         // [st][ b*(8*P) + c*P + p ]   (channel-major, pre-scaled)
__device__ float g_k[4][8 * 8192];         // same layout
__device__ float g_v[4][8192 * 64];        // [st][ (b*P+p)*64 + c ]      (point-major)
__device__ float g_accp[12 * 8192][64];    // split-K partial numerators
__device__ float g_denp[12 * 8192];        // split-K partial denominators
__device__ float g_ctx[8192 * 256];        // [pos][st*64+c]

// ---------------- f32x2 helpers ----------------
__device__ __forceinline__ ull fma2(ull a, ull b, ull c) {
    ull d;
    asm("fma.rn.f32x2 %0, %1, %2, %3;" : "=l"(d) : "l"(a), "l"(b), "l"(c));
    return d;
}
__device__ __forceinline__ ull pack2(float x, float y) {
    ull d;
    asm("mov.b64 %0, {%1, %2};" : "=l"(d) : "f"(x), "f"(y));
    return d;
}
__device__ __forceinline__ float2 unpack2(ull a) {
    float2 f;
    asm("mov.b64 {%0, %1}, %2;" : "=f"(f.x), "=f"(f.y) : "l"(a));
    return f;
}
__device__ __forceinline__ float ex2(float x) {
    float y;
    asm("ex2.approx.f32 %0, %1;" : "=f"(y) : "f"(x));
    return y;
}

// ---------------- 1. fold BN affine + softmax scale into weights ----------------
__global__ void fold_kernel(const float* __restrict__ Wq, const float* __restrict__ bq,
                            const float* __restrict__ gq, const float* __restrict__ beq,
                            const float* __restrict__ Wk, const float* __restrict__ bk,
                            const float* __restrict__ gk, const float* __restrict__ bek,
                            const float* __restrict__ Wv, const float* __restrict__ bv) {
    int st = blockIdx.x, o = threadIdx.x;
    // kc^-0.5 * log2(e): fold softmax scale + exp2 conversion into q
    const float SCALE = 0.35355339059327373f * 1.4426950408889634f;
    if (o < 8) {
        float g = gq[st * 8 + o];
        for (int c = 0; c < 64; c++)
            g_Wf[st][o][c] = g * Wq[(st * 8 + o) * 64 + c] * SCALE;
        g_bf[st][o] = (g * bq[st * 8 + o] + beq[st * 8 + o]) * SCALE;
    } else if (o < 16) {
        int i = o - 8;
        float g = gk[st * 8 + i];
        for (int c = 0; c < 64; c++)
            g_Wf[st][o][c] = g * Wk[(st * 8 + i) * 64 + c];
        g_bf[st][o] = g * bk[st * 8 + i] + bek[st * 8 + i];
    } else {
        int i = o - 16;
        for (int c = 0; c < 64; c++)
            g_Wf[st][o][c] = Wv[(st * 64 + i) * 64 + c];
        g_bf[st][o] = bv[st * 64 + i];
    }
}

// ---------------- 2. projections into blocked layouts ----------------
__global__ void __launch_bounds__(128) proj_kernel(const float* __restrict__ x1,
                                                   const float* __restrict__ x2) {
    int t = threadIdx.x;
    int pos = blockIdx.x * 128 + t;
    int h = pos >> 7, w2 = pos & 127;
    int w = w2 & 63, hv = w2 >> 6;  // hv = which image half
    const float* xsrc = hv ? x2 : x1;

    float xreg[64];
#pragma unroll
    for (int c = 0; c < 64; c++) xreg[c] = xsrc[c * 4096 + h * 64 + w];

    for (int st = 0; st < 4; st++) {
        int shift = 6 - st;
        int P = 8192 >> (2 * st);
        int m = (1 << shift) - 1;
        int si = h >> shift, hi = h & m;
        int sj = w >> shift, wi = w & m;
        int b = (si << st) + sj;
        int p = (((hi << shift) + wi) << 1) | hv;

        const float(*Wst)[64] = g_Wf[st];
        const float* bst = g_bf[st];
        float* qdst = g_q[st] + b * (8 * P);
        float* kdst = g_k[st] + b * (8 * P);
        for (int o = 0; o < 8; o++) {
            float aq = bst[o], ak = bst[8 + o];
#pragma unroll
            for (int c = 0; c < 64; c++) {
                float xv = xreg[c];
                aq += Wst[o][c] * xv;
                ak += Wst[8 + o][c] * xv;
            }
            qdst[o * P + p] = aq;
            kdst[o * P + p] = ak;
        }
        float* vdst = g_v[st] + (b * P + p) * 64;
        for (int o = 0; o < 64; o += 4) {
            float a0 = bst[16 + o], a1 = bst[17 + o], a2 = bst[18 + o], a3 = bst[19 + o];
#pragma unroll
            for (int c = 0; c < 64; c++) {
                float xv = xreg[c];
                a0 += Wst[16 + o][c] * xv;
                a1 += Wst[17 + o][c] * xv;
                a2 += Wst[18 + o][c] * xv;
                a3 += Wst[19 + o][c] * xv;
            }
            float4 a;
            a.x = a0; a.y = a1; a.z = a2; a.w = a3;
            *(float4*)(vdst + o) = a;
        }
    }
}

// ---------------- 3. flash attention (no max-subtraction; split-K additive) ----------------
// grid = 768 CTAs: st0: 512 (qt64 x ks8), st1: 128 (b4 x qt16 x ks2), st2: 64, st3: 64
// 64 threads, 2 queries per thread (128 queries per CTA)
__global__ void __launch_bounds__(64) flash_kernel() {
    int bid = blockIdx.x, t = threadIdx.x;
    int st, local, KS, poff;
    if (bid < 512)      { st = 0; local = bid;       KS = 8; poff = 0; }
    else if (bid < 640) { st = 1; local = bid - 512; KS = 2; poff = 8 * 8192; }
    else if (bid < 704) { st = 2; local = bid - 640; KS = 1; poff = 10 * 8192; }
    else                { st = 3; local = bid - 704; KS = 1; poff = 11 * 8192; }
    int P = 8192 >> (2 * st);
    int QT = P >> 7;               // query tiles per block (st3 -> 1)
    int ks = local % KS; local /= KS;
    int qt = local % QT;
    int b = local / QT;
    int Klen = P / KS;
    int k0 = ks * Klen;

    const float* qbase = g_q[st] + b * (8 * P);
    const float* kbase = g_k[st] + b * (8 * P);
    const float* vbase = g_v[st] + (b * P) * 64;

    int qA = qt * 128 + t;
    int qB = qA + 64;

    ull qA2[8], qB2[8];
#pragma unroll
    for (int c = 0; c < 8; c++) {
        float a = qbase[c * P + qA];
        float bb = qbase[c * P + qB];
        qA2[c] = pack2(a, a);
        qB2[c] = pack2(bb, bb);
    }
    ull accA[32], accB[32];
#pragma unroll
    for (int i = 0; i < 32; i++) { accA[i] = 0ull; accB[i] = 0ull; }
    float denA = 0.f, denB = 0.f;

    __shared__ __align__(16) float Ks[8][128];
    __shared__ __align__(16) float Vs[128 * 64];

    for (int kt = 0; kt < Klen; kt += 128) {
        __syncthreads();
        // load K tile: 8 x 128
        {
            int hh = t >> 5;
            int j = (t & 31) * 4;
#pragma unroll
            for (int cc = 0; cc < 4; cc++) {
                int c = cc * 2 + hh;
                *(float4*)&Ks[c][j] = *(const float4*)&kbase[c * P + k0 + kt + j];
            }
        }
        // load V tile: 128 x 64 (linear copy, point-major both sides)
        {
            const float4* src = (const float4*)(vbase + (k0 + kt) * 64);
            float4* dst = (float4*)Vs;
#pragma unroll
            for (int i = 0; i < 32; i++) dst[t + i * 64] = src[t + i * 64];
        }
        __syncthreads();

#pragma unroll 1
        for (int j = 0; j < 128; j += 4) {
            // dots for 4 keys, both queries, via f32x2 along key pairs
            ull dA01 = 0ull, dA23 = 0ull, dB01 = 0ull, dB23 = 0ull;
#pragma unroll
            for (int c = 0; c < 8; c++) {
                ulonglong2 kf = *(const ulonglong2*)&Ks[c][j];  // (k_j,k_j+1),(k_j+2,k_j+3)
                dA01 = fma2(qA2[c], kf.x, dA01);
                dA23 = fma2(qA2[c], kf.y, dA23);
                dB01 = fma2(qB2[c], kf.x, dB01);
                dB23 = fma2(qB2[c], kf.y, dB23);
            }
            float2 sA01 = unpack2(dA01), sA23 = unpack2(dA23);
            float2 sB01 = unpack2(dB01), sB23 = unpack2(dB23);
            float eA0 = ex2(sA01.x), eA1 = ex2(sA01.y), eA2 = ex2(sA23.x), eA3 = ex2(sA23.y);
            float eB0 = ex2(sB01.x), eB1 = ex2(sB01.y), eB2 = ex2(sB23.x), eB3 = ex2(sB23.y);
            denA += (eA0 + eA1) + (eA2 + eA3);
            denB += (eB0 + eB1) + (eB2 + eB3);
            ull eA[4] = {pack2(eA0, eA0), pack2(eA1, eA1), pack2(eA2, eA2), pack2(eA3, eA3)};
            ull eB[4] = {pack2(eB0, eB0), pack2(eB1, eB1), pack2(eB2, eB2), pack2(eB3, eB3)};
#pragma unroll
            for (int jj = 0; jj < 4; jj++) {
                const ulonglong2* vrow = (const ulonglong2*)&Vs[(j + jj) * 64];
#pragma unroll
                for (int i = 0; i < 16; i++) {
                    ulonglong2 vv = vrow[i];  // channels 4i..4i+3 as two f32x2
                    accA[2 * i]     = fma2(eA[jj], vv.x, accA[2 * i]);
                    accA[2 * i + 1] = fma2(eA[jj], vv.y, accA[2 * i + 1]);
                    accB[2 * i]     = fma2(eB[jj], vv.x, accB[2 * i]);
                    accB[2 * i + 1] = fma2(eB[jj], vv.y, accB[2 * i + 1]);
                }
            }
        }
    }

    // write partials (raw numerator + denominator; reduce kernel normalizes)
    int rowA = poff + ks * 8192 + b * P + qA;
    int rowB = poff + ks * 8192 + b * P + qB;
    float* dA = g_accp[rowA];
    float* dB = g_accp[rowB];
#pragma unroll
    for (int i = 0; i < 16; i++) {
        float2 a0 = unpack2(accA[2 * i]), a1 = unpack2(accA[2 * i + 1]);
        float4 v;
        v.x = a0.x; v.y = a0.y; v.z = a1.x; v.w = a1.y;
        *(float4*)(dA + 4 * i) = v;
        float2 b0 = unpack2(accB[2 * i]), b1 = unpack2(accB[2 * i + 1]);
        float4 u;
        u.x = b0.x; u.y = b0.y; u.z = b1.x; u.w = b1.y;
        *(float4*)(dB + 4 * i) = u;
    }
    g_denp[rowA] = denA;
    g_denp[rowB] = denB;
}

// ---------------- 4. reduce splits, normalize, scatter to spatial [pos][256] ----------------
__global__ void __launch_bounds__(128) reduce_kernel() {
    int st = blockIdx.y;
    int qi = blockIdx.x * 128 + threadIdx.x;
    int KS = (st == 0) ? 8 : (st == 1) ? 2 : 1;
    int poff = (st == 0) ? 0 : (st == 1) ? 8 * 8192 : (st == 2) ? 10 * 8192 : 11 * 8192;
    int row0 = poff + qi;

    float den = 0.f;
    for (int ksp = 0; ksp < KS; ksp++) den += g_denp[row0 + ksp * 8192];
    float inv = 1.0f / den;

    int shift2 = 13 - 2 * st;
    int P = 1 << shift2;
    int b = qi >> shift2, p = qi & (P - 1);
    int shift = 6 - st;
    int si = b >> st, sj = b & ((1 << st) - 1);
    int hv = p & 1, tt = p >> 1;
    int hi = tt >> shift, wi = tt & ((1 << shift) - 1);
    int h = (si << shift) + hi;
    int w2 = (sj << shift) + wi + (hv << 6);
    int pos = (h << 7) + w2;

    float* dst = g_ctx + pos * 256 + st * 64;
    for (int c = 0; c < 64; c += 4) {
        float4 s = make_float4(0.f, 0.f, 0.f, 0.f);
        for (int ksp = 0; ksp < KS; ksp++) {
            float4 a = *(const float4*)&g_accp[row0 + ksp * 8192][c];
            s.x += a.x; s.y += a.y; s.z += a.z; s.w += a.w;
        }
        s.x *= inv; s.y *= inv; s.z *= inv; s.w *= inv;
        *(float4*)(dst + c) = s;
    }
}

// ---------------- 5. final 1x1 conv (64 out x 256 in) + split halves ----------------
__global__ void __launch_bounds__(128) conv_kernel(const float* __restrict__ Wo,
                                                   float* __restrict__ out) {
    __shared__ float ws[64 * 65];
    __shared__ float cs[64 * 65];
    int t = threadIdx.x;
    int pos0 = blockIdx.x * 64;
    int og = t >> 4, pg = t & 15;

    float acc[8][4];
#pragma unroll
    for (int i = 0; i < 8; i++)
#pragma unroll
        for (int j = 0; j < 4; j++) acc[i][j] = 0.f;

    for (int ci0 = 0; ci0 < 256; ci0 += 64) {
        __syncthreads();
        for (int r = 0; r < 32; r++) {
            int idx = r * 128 + t;
            int a = idx >> 6, cc = idx & 63;
            ws[a * 65 + cc] = Wo[a * 256 + ci0 + cc];
            cs[a * 65 + cc] = g_ctx[(pos0 + a) * 256 + ci0 + cc];
        }
        __syncthreads();
#pragma unroll 4
        for (int cc = 0; cc < 64; cc++) {
            float wr[8], xr[4];
#pragma unroll
            for (int i = 0; i < 8; i++) wr[i] = ws[(og * 8 + i) * 65 + cc];
#pragma unroll
            for (int j = 0; j < 4; j++) xr[j] = cs[(pg * 4 + j) * 65 + cc];
#pragma unroll
            for (int i = 0; i < 8; i++)
#pragma unroll
                for (int j = 0; j < 4; j++) acc[i][j] += wr[i] * xr[j];
        }
    }

#pragma unroll
    for (int i = 0; i < 8; i++) {
        int o = og * 8 + i;
#pragma unroll
        for (int j = 0; j < 4; j++) {
            int pos = pos0 + pg * 4 + j;
            int h = pos >> 7, w2 = pos & 127;
            int idx = (w2 < 64) ? (o * 4096 + h * 64 + w2)
                                : (262144 + o * 4096 + h * 64 + (w2 - 64));
            out[idx] = acc[i][j];
        }
    }
}

// ---------------- launch ----------------
extern "C" void kernel_launch(void* const* d_in, const int* in_sizes, int n_in,
                              void* d_out, int out_size) {
    const float* x1 = (const float*)d_in[0];
    const float* x2 = (const float*)d_in[1];
    const float* Wq = (const float*)d_in[2];
    const float* bq = (const float*)d_in[3];
    const float* gq = (const float*)d_in[4];
    const float* beq = (const float*)d_in[5];
    const float* Wk = (const float*)d_in[6];
    const float* bk = (const float*)d_in[7];
    const float* gk = (const float*)d_in[8];
    const float* bek = (const float*)d_in[9];
    const float* Wv = (const float*)d_in[10];
    const float* bv = (const float*)d_in[11];
    const float* Wo = (const float*)d_in[12];
    float* out = (float*)d_out;

    fold_kernel<<<4, 80>>>(Wq, bq, gq, beq, Wk, bk, gk, bek, Wv, bv);
    proj_kernel<<<64, 128>>>(x1, x2);
    flash_kernel<<<768, 64>>>();
    reduce_kernel<<<dim3(64, 4), 128>>>();
    conv_kernel<<<128, 128>>>(Wo, out);
}

// round 3
// speedup vs baseline: 1.6550x; 1.6550x over previous
#include <cuda_runtime.h>
#include <cstdint>

typedef unsigned long long ull;

// ---------------- static scratch (no allocations allowed) ----------------
__device__ float g_Wf[4][80][64];          // folded weights: [stage][o<8:q,8..15:k,16..79:v][c]
__device__ float g_bf[4][80];              // folded biases
__device__ float g_q[4][8 * 8192];         // [st][ b*(8*P) + c*P + p ]   (channel-major, pre-scaled)
__device__ float g_k[4][8 * 8192];         // same layout
__device__ float g_v[4][8192 * 64];        // [st][ (b*P+p)*64 + c ]      (point-major)
__device__ float g_accp[10 * 8192][64];    // split-K partial numerators (stages 0,1 only)
__device__ float g_denp[10 * 8192];        // split-K partial denominators
__device__ float g_ctx[8192 * 256];        // [pos][st*64+c]

// ---------------- f32x2 helpers ----------------
__device__ __forceinline__ ull fma2(ull a, ull b, ull c) {
    ull d;
    asm("fma.rn.f32x2 %0, %1, %2, %3;" : "=l"(d) : "l"(a), "l"(b), "l"(c));
    return d;
}
__device__ __forceinline__ ull pack2(float x, float y) {
    ull d;
    asm("mov.b64 %0, {%1, %2};" : "=l"(d) : "f"(x), "f"(y));
    return d;
}
__device__ __forceinline__ float2 unpack2(ull a) {
    float2 f;
    asm("mov.b64 {%0, %1}, %2;" : "=f"(f.x), "=f"(f.y) : "l"(a));
    return f;
}
__device__ __forceinline__ float ex2(float x) {
    float y;
    asm("ex2.approx.f32 %0, %1;" : "=f"(y) : "f"(x));
    return y;
}

// ---------------- 1. fold BN affine + softmax scale into weights ----------------
__global__ void fold_kernel(const float* __restrict__ Wq, const float* __restrict__ bq,
                            const float* __restrict__ gq, const float* __restrict__ beq,
                            const float* __restrict__ Wk, const float* __restrict__ bk,
                            const float* __restrict__ gk, const float* __restrict__ bek,
                            const float* __restrict__ Wv, const float* __restrict__ bv) {
    int st = blockIdx.x, o = threadIdx.x;
    // kc^-0.5 * log2(e): fold softmax scale + exp2 conversion into q
    const float SCALE = 0.35355339059327373f * 1.4426950408889634f;
    if (o < 8) {
        float g = gq[st * 8 + o];
        for (int c = 0; c < 64; c++)
            g_Wf[st][o][c] = g * Wq[(st * 8 + o) * 64 + c] * SCALE;
        g_bf[st][o] = (g * bq[st * 8 + o] + beq[st * 8 + o]) * SCALE;
    } else if (o < 16) {
        int i = o - 8;
        float g = gk[st * 8 + i];
        for (int c = 0; c < 64; c++)
            g_Wf[st][o][c] = g * Wk[(st * 8 + i) * 64 + c];
        g_bf[st][o] = g * bk[st * 8 + i] + bek[st * 8 + i];
    } else {
        int i = o - 16;
        for (int c = 0; c < 64; c++)
            g_Wf[st][o][c] = Wv[(st * 64 + i) * 64 + c];
        g_bf[st][o] = bv[st * 64 + i];
    }
}

// ---------------- 2. projections into blocked layouts (weights in smem) ----------------
__global__ void __launch_bounds__(128) proj_kernel(const float* __restrict__ x1,
                                                   const float* __restrict__ x2) {
    __shared__ float sW[80][64];
    __shared__ float sb[80];
    int t = threadIdx.x;
    int pos = blockIdx.x * 128 + t;
    int h = pos >> 7, w2 = pos & 127;
    int w = w2 & 63, hv = w2 >> 6;  // hv = which image half
    const float* xsrc = hv ? x2 : x1;

    float xreg[64];
#pragma unroll
    for (int c = 0; c < 64; c++) xreg[c] = xsrc[c * 4096 + h * 64 + w];

    for (int st = 0; st < 4; st++) {
        __syncthreads();
        // stage weights into smem
        for (int i = 0; i < 40; i++) {
            int idx = i * 128 + t;
            ((float*)sW)[idx] = ((const float*)g_Wf[st])[idx];
        }
        if (t < 80) sb[t] = g_bf[st][t];
        __syncthreads();

        int shift = 6 - st;
        int P = 8192 >> (2 * st);
        int m = (1 << shift) - 1;
        int si = h >> shift, hi = h & m;
        int sj = w >> shift, wi = w & m;
        int b = (si << st) + sj;
        int p = (((hi << shift) + wi) << 1) | hv;

        float* qdst = g_q[st] + b * (8 * P);
        float* kdst = g_k[st] + b * (8 * P);
        for (int o = 0; o < 8; o++) {
            float aq = sb[o], ak = sb[8 + o];
#pragma unroll
            for (int c = 0; c < 64; c++) {
                float xv = xreg[c];
                aq += sW[o][c] * xv;
                ak += sW[8 + o][c] * xv;
            }
            qdst[o * P + p] = aq;
            kdst[o * P + p] = ak;
        }
        float* vdst = g_v[st] + (b * P + p) * 64;
        for (int o = 0; o < 64; o += 4) {
            float a0 = sb[16 + o], a1 = sb[17 + o], a2 = sb[18 + o], a3 = sb[19 + o];
#pragma unroll
            for (int c = 0; c < 64; c++) {
                float xv = xreg[c];
                a0 += sW[16 + o][c] * xv;
                a1 += sW[17 + o][c] * xv;
                a2 += sW[18 + o][c] * xv;
                a3 += sW[19 + o][c] * xv;
            }
            float4 a;
            a.x = a0; a.y = a1; a.z = a2; a.w = a3;
            *(float4*)(vdst + o) = a;
        }
    }
}

// ---------------- 3. flash attention: 1 query/thread, 128 threads/CTA ----------------
// grid = 768 CTAs: st0: 512 (qt64 x ks8), st1: 128 (b4 x qt16 x ks2), st2: 64, st3: 64
__global__ void __launch_bounds__(128, 3) flash_kernel() {
    int bid = blockIdx.x, t = threadIdx.x;
    int st, local, KS, poff;
    if (bid < 512)      { st = 0; local = bid;       KS = 8; poff = 0; }
    else if (bid < 640) { st = 1; local = bid - 512; KS = 2; poff = 8 * 8192; }
    else if (bid < 704) { st = 2; local = bid - 640; KS = 1; poff = 0; }
    else                { st = 3; local = bid - 704; KS = 1; poff = 0; }
    int P = 8192 >> (2 * st);
    int QT = P >> 7;               // query tiles per block (st3 -> 1)
    int ks = local % KS; local /= KS;
    int qt = local % QT;
    int b = local / QT;
    int Klen = P / KS;
    int k0 = ks * Klen;

    const float* qbase = g_q[st] + b * (8 * P);
    const float* kbase = g_k[st] + b * (8 * P);
    const float* vbase = g_v[st] + (b * P) * 64;

    int q = qt * 128 + t;

    ull q2[8];
#pragma unroll
    for (int c = 0; c < 8; c++) {
        float a = qbase[c * P + q];
        q2[c] = pack2(a, a);
    }
    ull acc[32];
#pragma unroll
    for (int i = 0; i < 32; i++) acc[i] = 0ull;
    float den = 0.f;

    __shared__ __align__(16) float Ks[8][128];
    __shared__ __align__(16) float Vs[128 * 64];

    for (int kt = 0; kt < Klen; kt += 128) {
        __syncthreads();
        // load K tile: 8 x 128 floats = 256 float4, 128 threads x 2
#pragma unroll
        for (int i = 0; i < 2; i++) {
            int idx = i * 128 + t;
            int c = idx >> 5;
            int j = (idx & 31) * 4;
            *(float4*)&Ks[c][j] = *(const float4*)&kbase[c * P + k0 + kt + j];
        }
        // load V tile: 128 x 64 floats = 2048 float4, 128 threads x 16
        {
            const float4* src = (const float4*)(vbase + (k0 + kt) * 64);
            float4* dst = (float4*)Vs;
#pragma unroll
            for (int i = 0; i < 16; i++) dst[t + i * 128] = src[t + i * 128];
        }
        __syncthreads();

#pragma unroll 1
        for (int j = 0; j < 128; j += 4) {
            // dots for 4 keys via f32x2 along key pairs
            ull d01 = 0ull, d23 = 0ull;
#pragma unroll
            for (int c = 0; c < 8; c++) {
                ulonglong2 kf = *(const ulonglong2*)&Ks[c][j];  // (k_j,k_j+1),(k_j+2,k_j+3)
                d01 = fma2(q2[c], kf.x, d01);
                d23 = fma2(q2[c], kf.y, d23);
            }
            float2 s01 = unpack2(d01), s23 = unpack2(d23);
            float e0 = ex2(s01.x), e1 = ex2(s01.y), e2v = ex2(s23.x), e3 = ex2(s23.y);
            den += (e0 + e1) + (e2v + e3);
            ull e[4] = {pack2(e0, e0), pack2(e1, e1), pack2(e2v, e2v), pack2(e3, e3)};
#pragma unroll
            for (int jj = 0; jj < 4; jj++) {
                const ulonglong2* vrow = (const ulonglong2*)&Vs[(j + jj) * 64];
#pragma unroll
                for (int i = 0; i < 16; i++) {
                    ulonglong2 vv = vrow[i];  // channels 4i..4i+3 as two f32x2
                    acc[2 * i]     = fma2(e[jj], vv.x, acc[2 * i]);
                    acc[2 * i + 1] = fma2(e[jj], vv.y, acc[2 * i + 1]);
                }
            }
        }
    }

    if (KS > 1) {
        // write raw partials; reduce kernel normalizes
        int row = poff + ks * 8192 + b * P + q;
        float* dA = g_accp[row];
#pragma unroll
        for (int i = 0; i < 16; i++) {
            float2 a0 = unpack2(acc[2 * i]), a1 = unpack2(acc[2 * i + 1]);
            float4 v;
            v.x = a0.x; v.y = a0.y; v.z = a1.x; v.w = a1.y;
            *(float4*)(dA + 4 * i) = v;
        }
        g_denp[row] = den;
    } else {
        // complete: normalize and scatter straight to g_ctx
        float inv = 1.0f / den;
        int shift = 6 - st;
        int si = b >> st, sj = b & ((1 << st) - 1);
        int hv = q & 1, tt = q >> 1;
        int hi = tt >> shift, wi = tt & ((1 << shift) - 1);
        int h = (si << shift) + hi;
        int w2 = (sj << shift) + wi + (hv << 6);
        int pos = (h << 7) + w2;
        float* dst = g_ctx + pos * 256 + st * 64;
#pragma unroll
        for (int i = 0; i < 16; i++) {
            float2 a0 = unpack2(acc[2 * i]), a1 = unpack2(acc[2 * i + 1]);
            float4 v;
            v.x = a0.x * inv; v.y = a0.y * inv; v.z = a1.x * inv; v.w = a1.y * inv;
            *(float4*)(dst + 4 * i) = v;
        }
    }
}

// ---------------- 4. reduce splits (stages 0,1), normalize, scatter ----------------
// block = 128 threads = 32 rows x 4 channel-groups of 16; grid.x = 8192/32 = 256
__global__ void __launch_bounds__(128) reduce_kernel() {
    int st = blockIdx.y;  // 0 or 1
    int t = threadIdx.x;
    int qi = blockIdx.x * 32 + (t >> 2);
    int cg = t & 3;
    int KS = (st == 0) ? 8 : 2;
    int poff = (st == 0) ? 0 : 8 * 8192;
    int row0 = poff + qi;

    float den = 0.f;
    for (int ksp = 0; ksp < KS; ksp++) den += g_denp[row0 + ksp * 8192];
    float inv = 1.0f / den;

    int shift2 = 13 - 2 * st;
    int Pb = 1 << shift2;
    int b = qi >> shift2, p = qi & (Pb - 1);
    int shift = 6 - st;
    int si = b >> st, sj = b & ((1 << st) - 1);
    int hv = p & 1, tt = p >> 1;
    int hi = tt >> shift, wi = tt & ((1 << shift) - 1);
    int h = (si << shift) + hi;
    int w2 = (sj << shift) + wi + (hv << 6);
    int pos = (h << 7) + w2;

    float* dst = g_ctx + pos * 256 + st * 64 + cg * 16;
#pragma unroll
    for (int c = 0; c < 16; c += 4) {
        float4 s = make_float4(0.f, 0.f, 0.f, 0.f);
        for (int ksp = 0; ksp < KS; ksp++) {
            float4 a = *(const float4*)&g_accp[row0 + ksp * 8192][cg * 16 + c];
            s.x += a.x; s.y += a.y; s.z += a.z; s.w += a.w;
        }
        s.x *= inv; s.y *= inv; s.z *= inv; s.w *= inv;
        *(float4*)(dst + c) = s;
    }
}

// ---------------- 5. final 1x1 conv (64 out x 256 in) + split halves ----------------
__global__ void __launch_bounds__(128) conv_kernel(const float* __restrict__ Wo,
                                                   float* __restrict__ out) {
    __shared__ float ws[64 * 65];
    __shared__ float cs[64 * 65];
    int t = threadIdx.x;
    int pos0 = blockIdx.x * 64;
    int og = t >> 4, pg = t & 15;

    float acc[8][4];
#pragma unroll
    for (int i = 0; i < 8; i++)
#pragma unroll
        for (int j = 0; j < 4; j++) acc[i][j] = 0.f;

    for (int ci0 = 0; ci0 < 256; ci0 += 64) {
        __syncthreads();
        for (int r = 0; r < 32; r++) {
            int idx = r * 128 + t;
            int a = idx >> 6, cc = idx & 63;
            ws[a * 65 + cc] = Wo[a * 256 + ci0 + cc];
            cs[a * 65 + cc] = g_ctx[(pos0 + a) * 256 + ci0 + cc];
        }
        __syncthreads();
#pragma unroll 4
        for (int cc = 0; cc < 64; cc++) {
            float wr[8], xr[4];
#pragma unroll
            for (int i = 0; i < 8; i++) wr[i] = ws[(og * 8 + i) * 65 + cc];
#pragma unroll
            for (int j = 0; j < 4; j++) xr[j] = cs[(pg * 4 + j) * 65 + cc];
#pragma unroll
            for (int i = 0; i < 8; i++)
#pragma unroll
                for (int j = 0; j < 4; j++) acc[i][j] += wr[i] * xr[j];
        }
    }

#pragma unroll
    for (int i = 0; i < 8; i++) {
        int o = og * 8 + i;
#pragma unroll
        for (int j = 0; j < 4; j++) {
            int pos = pos0 + pg * 4 + j;
            int h = pos >> 7, w2 = pos & 127;
            int idx = (w2 < 64) ? (o * 4096 + h * 64 + w2)
                                : (262144 + o * 4096 + h * 64 + (w2 - 64));
            out[idx] = acc[i][j];
        }
    }
}

// ---------------- launch ----------------
extern "C" void kernel_launch(void* const* d_in, const int* in_sizes, int n_in,
                              void* d_out, int out_size) {
    const float* x1 = (const float*)d_in[0];
    const float* x2 = (const float*)d_in[1];
    const float* Wq = (const float*)d_in[2];
    const float* bq = (const float*)d_in[3];
    const float* gq = (const float*)d_in[4];
    const float* beq = (const float*)d_in[5];
    const float* Wk = (const float*)d_in[6];
    const float* bk = (const float*)d_in[7];
    const float* gk = (const float*)d_in[8];
    const float* bek = (const float*)d_in[9];
    const float* Wv = (const float*)d_in[10];
    const float* bv = (const float*)d_in[11];
    const float* Wo = (const float*)d_in[12];
    float* out = (float*)d_out;

    fold_kernel<<<4, 80>>>(Wq, bq, gq, beq, Wk, bk, gk, bek, Wv, bv);
    proj_kernel<<<64, 128>>>(x1, x2);
    flash_kernel<<<768, 128>>>();
    reduce_kernel<<<dim3(256, 2), 128>>>();
    conv_kernel<<<128, 128>>>(Wo, out);
}

// round 4
// speedup vs baseline: 1.6779x; 1.0139x over previous
#include <cuda_runtime.h>
#include <cstdint>

typedef unsigned long long ull;

// ---------------- static scratch (no allocations allowed) ----------------
__device__ float g_Wf[4][80][64];          // folded weights: [stage][o<8:q,8..15:k,16..79:v][c]
__device__ float g_bf[4][80];              // folded biases
__device__ float g_q[4][8 * 8192];         // [st][ b*(8*P) + c*P + p ]   (channel-major, pre-scaled)
__device__ float g_k[4][8 * 8192];         // same layout
__device__ float g_v[4][8192 * 64];        // [st][ (b*P+p)*64 + c ]      (point-major)
__device__ float g_accp[10 * 8192][64];    // split-K partial numerators (stages 0,1 only)
__device__ float g_denp[10 * 8192];        // split-K partial denominators
__device__ float g_ctx[8192 * 256];        // [pos][st*64+c]

// ---------------- f32x2 helpers ----------------
__device__ __forceinline__ ull fma2(ull a, ull b, ull c) {
    ull d;
    asm("fma.rn.f32x2 %0, %1, %2, %3;" : "=l"(d) : "l"(a), "l"(b), "l"(c));
    return d;
}
__device__ __forceinline__ ull pack2(float x, float y) {
    ull d;
    asm("mov.b64 %0, {%1, %2};" : "=l"(d) : "f"(x), "f"(y));
    return d;
}
__device__ __forceinline__ float2 unpack2(ull a) {
    float2 f;
    asm("mov.b64 {%0, %1}, %2;" : "=f"(f.x), "=f"(f.y) : "l"(a));
    return f;
}
__device__ __forceinline__ float ex2(float x) {
    float y;
    asm("ex2.approx.f32 %0, %1;" : "=f"(y) : "f"(x));
    return y;
}

// ---------------- 1. fold BN affine + softmax scale into weights ----------------
__global__ void fold_kernel(const float* __restrict__ Wq, const float* __restrict__ bq,
                            const float* __restrict__ gq, const float* __restrict__ beq,
                            const float* __restrict__ Wk, const float* __restrict__ bk,
                            const float* __restrict__ gk, const float* __restrict__ bek,
                            const float* __restrict__ Wv, const float* __restrict__ bv) {
    int st = blockIdx.x, o = threadIdx.x;
    // kc^-0.5 * log2(e): fold softmax scale + exp2 conversion into q
    const float SCALE = 0.35355339059327373f * 1.4426950408889634f;
    if (o < 8) {
        float g = gq[st * 8 + o];
        for (int c = 0; c < 64; c++)
            g_Wf[st][o][c] = g * Wq[(st * 8 + o) * 64 + c] * SCALE;
        g_bf[st][o] = (g * bq[st * 8 + o] + beq[st * 8 + o]) * SCALE;
    } else if (o < 16) {
        int i = o - 8;
        float g = gk[st * 8 + i];
        for (int c = 0; c < 64; c++)
            g_Wf[st][o][c] = g * Wk[(st * 8 + i) * 64 + c];
        g_bf[st][o] = g * bk[st * 8 + i] + bek[st * 8 + i];
    } else {
        int i = o - 16;
        for (int c = 0; c < 64; c++)
            g_Wf[st][o][c] = Wv[(st * 64 + i) * 64 + c];
        g_bf[st][o] = bv[st * 64 + i];
    }
}

// ---------------- 2. projections into blocked layouts (weights in smem) ----------------
__global__ void __launch_bounds__(128) proj_kernel(const float* __restrict__ x1,
                                                   const float* __restrict__ x2) {
    __shared__ float sW[80][64];
    __shared__ float sb[80];
    int t = threadIdx.x;
    int pos = blockIdx.x * 128 + t;
    int h = pos >> 7, w2 = pos & 127;
    int w = w2 & 63, hv = w2 >> 6;  // hv = which image half
    const float* xsrc = hv ? x2 : x1;

    float xreg[64];
#pragma unroll
    for (int c = 0; c < 64; c++) xreg[c] = xsrc[c * 4096 + h * 64 + w];

    for (int st = 0; st < 4; st++) {
        __syncthreads();
        // stage weights into smem
        for (int i = 0; i < 40; i++) {
            int idx = i * 128 + t;
            ((float*)sW)[idx] = ((const float*)g_Wf[st])[idx];
        }
        if (t < 80) sb[t] = g_bf[st][t];
        __syncthreads();

        int shift = 6 - st;
        int P = 8192 >> (2 * st);
        int m = (1 << shift) - 1;
        int si = h >> shift, hi = h & m;
        int sj = w >> shift, wi = w & m;
        int b = (si << st) + sj;
        int p = (((hi << shift) + wi) << 1) | hv;

        float* qdst = g_q[st] + b * (8 * P);
        float* kdst = g_k[st] + b * (8 * P);
        for (int o = 0; o < 8; o++) {
            float aq = sb[o], ak = sb[8 + o];
#pragma unroll
            for (int c = 0; c < 64; c++) {
                float xv = xreg[c];
                aq += sW[o][c] * xv;
                ak += sW[8 + o][c] * xv;
            }
            qdst[o * P + p] = aq;
            kdst[o * P + p] = ak;
        }
        float* vdst = g_v[st] + (b * P + p) * 64;
        for (int o = 0; o < 64; o += 4) {
            float a0 = sb[16 + o], a1 = sb[17 + o], a2 = sb[18 + o], a3 = sb[19 + o];
#pragma unroll
            for (int c = 0; c < 64; c++) {
                float xv = xreg[c];
                a0 += sW[16 + o][c] * xv;
                a1 += sW[17 + o][c] * xv;
                a2 += sW[18 + o][c] * xv;
                a3 += sW[19 + o][c] * xv;
            }
            float4 a;
            a.x = a0; a.y = a1; a.z = a2; a.w = a3;
            *(float4*)(vdst + o) = a;
        }
    }
}

// ---------------- 3. flash attention: smem-staged E GEMM ----------------
// grid = 768 CTAs: st0: 512 (qt64 x ks8), st1: 128 (b4 x qt16 x ks2), st2: 64, st3: 64
// 128 threads; per CTA: 128 queries. Per 32-key tile:
//   phase1: thread t computes exp-scores for query t, writes duplicated (e,e) pairs to Es
//   phase2: 8q x 8c register-tiled GEMM  acc += Es * V
__global__ void __launch_bounds__(128, 4) flash_kernel() {
    int bid = blockIdx.x, t = threadIdx.x;
    int st, local, KS, poff;
    if (bid < 512)      { st = 0; local = bid;       KS = 8; poff = 0; }
    else if (bid < 640) { st = 1; local = bid - 512; KS = 2; poff = 8 * 8192; }
    else if (bid < 704) { st = 2; local = bid - 640; KS = 1; poff = 0; }
    else                { st = 3; local = bid - 704; KS = 1; poff = 0; }
    int P = 8192 >> (2 * st);
    int QT = P >> 7;               // query tiles per block
    int ks = local % KS; local /= KS;
    int qt = local % QT;
    int b = local / QT;
    int Klen = P / KS;
    int k0 = ks * Klen;

    const float* qbase = g_q[st] + b * (8 * P);
    const float* kbase = g_k[st] + b * (8 * P);
    const float* vbase = g_v[st] + (b * P) * 64;

    int q = qt * 128 + t;       // this thread's query (phase 1)
    int qg = t >> 3, cg = t & 7;  // phase-2 tile coords: queries qg*8..+7, channels cg*8..+7

    ull q2[8];
#pragma unroll
    for (int c = 0; c < 8; c++) {
        float a = qbase[c * P + q];
        q2[c] = pack2(a, a);
    }
    ull acc[8][4];
#pragma unroll
    for (int i = 0; i < 8; i++)
#pragma unroll
        for (int j = 0; j < 4; j++) acc[i][j] = 0ull;
    float den = 0.f;

    __shared__ __align__(16) float Ks[8][32];
    __shared__ __align__(16) float Vs[32][64];
    __shared__ __align__(16) ull Es[32][128];
    __shared__ float den_s[128];

    for (int kt = 0; kt < Klen; kt += 32) {
        __syncthreads();
        // load K tile: 8 x 32 floats = 64 float4 (threads 0..63)
        if (t < 64) {
            int c = t >> 3;
            int j = (t & 7) * 4;
            *(float4*)&Ks[c][j] = *(const float4*)&kbase[c * P + k0 + kt + j];
        }
        // load V tile: 32 x 64 floats = 512 float4
        {
            const float4* src = (const float4*)(vbase + (k0 + kt) * 64);
            float4* dst = (float4*)Vs;
#pragma unroll
            for (int i = 0; i < 4; i++) dst[t + i * 128] = src[t + i * 128];
        }
        __syncthreads();

        // phase 1: scores for query t vs 32 keys, write duplicated exp pairs
#pragma unroll
        for (int j = 0; j < 32; j += 4) {
            ull d01 = 0ull, d23 = 0ull;
#pragma unroll
            for (int c = 0; c < 8; c++) {
                ulonglong2 kf = *(const ulonglong2*)&Ks[c][j];
                d01 = fma2(q2[c], kf.x, d01);
                d23 = fma2(q2[c], kf.y, d23);
            }
            float2 s01 = unpack2(d01), s23 = unpack2(d23);
            float e0 = ex2(s01.x), e1 = ex2(s01.y), e2v = ex2(s23.x), e3 = ex2(s23.y);
            den += (e0 + e1) + (e2v + e3);
            Es[j + 0][t] = pack2(e0, e0);
            Es[j + 1][t] = pack2(e1, e1);
            Es[j + 2][t] = pack2(e2v, e2v);
            Es[j + 3][t] = pack2(e3, e3);
        }
        __syncthreads();

        // phase 2: acc[8q][8c] += E * V over 32 keys
#pragma unroll 2
        for (int k = 0; k < 32; k++) {
            ulonglong2 v01 = *(const ulonglong2*)&Vs[k][cg * 8];
            ulonglong2 v23 = *(const ulonglong2*)&Vs[k][cg * 8 + 4];
#pragma unroll
            for (int qp = 0; qp < 4; qp++) {
                ulonglong2 e2 = *(const ulonglong2*)&Es[k][qg * 8 + qp * 2];
                acc[qp * 2][0] = fma2(e2.x, v01.x, acc[qp * 2][0]);
                acc[qp * 2][1] = fma2(e2.x, v01.y, acc[qp * 2][1]);
                acc[qp * 2][2] = fma2(e2.x, v23.x, acc[qp * 2][2]);
                acc[qp * 2][3] = fma2(e2.x, v23.y, acc[qp * 2][3]);
                acc[qp * 2 + 1][0] = fma2(e2.y, v01.x, acc[qp * 2 + 1][0]);
                acc[qp * 2 + 1][1] = fma2(e2.y, v01.y, acc[qp * 2 + 1][1]);
                acc[qp * 2 + 1][2] = fma2(e2.y, v23.x, acc[qp * 2 + 1][2]);
                acc[qp * 2 + 1][3] = fma2(e2.y, v23.y, acc[qp * 2 + 1][3]);
            }
        }
    }

    den_s[t] = den;
    if (KS > 1) g_denp[poff + ks * 8192 + b * P + q] = den;
    __syncthreads();

    if (KS > 1) {
        // write raw partial numerators; reduce kernel normalizes
#pragma unroll
        for (int i = 0; i < 8; i++) {
            int qq = qt * 128 + qg * 8 + i;
            int row = poff + ks * 8192 + b * P + qq;
            float2 a0 = unpack2(acc[i][0]), a1 = unpack2(acc[i][1]);
            float2 a2 = unpack2(acc[i][2]), a3 = unpack2(acc[i][3]);
            float4 v0; v0.x = a0.x; v0.y = a0.y; v0.z = a1.x; v0.w = a1.y;
            float4 v1; v1.x = a2.x; v1.y = a2.y; v1.z = a3.x; v1.w = a3.y;
            *(float4*)&g_accp[row][cg * 8] = v0;
            *(float4*)&g_accp[row][cg * 8 + 4] = v1;
        }
    } else {
        // complete: normalize and scatter straight to g_ctx
        int shift = 6 - st;
        int si = b >> st, sj = b & ((1 << st) - 1);
#pragma unroll
        for (int i = 0; i < 8; i++) {
            int p = qt * 128 + qg * 8 + i;
            float inv = 1.0f / den_s[qg * 8 + i];
            int hv = p & 1, tt2 = p >> 1;
            int hi = tt2 >> shift, wi = tt2 & ((1 << shift) - 1);
            int h = (si << shift) + hi;
            int w2 = (sj << shift) + wi + (hv << 6);
            int pos = (h << 7) + w2;
            float* dst = g_ctx + pos * 256 + st * 64 + cg * 8;
            float2 a0 = unpack2(acc[i][0]), a1 = unpack2(acc[i][1]);
            float2 a2 = unpack2(acc[i][2]), a3 = unpack2(acc[i][3]);
            float4 v0; v0.x = a0.x * inv; v0.y = a0.y * inv; v0.z = a1.x * inv; v0.w = a1.y * inv;
            float4 v1; v1.x = a2.x * inv; v1.y = a2.y * inv; v1.z = a3.x * inv; v1.w = a3.y * inv;
            *(float4*)(dst) = v0;
            *(float4*)(dst + 4) = v1;
        }
    }
}

// ---------------- 4. reduce splits (stages 0,1), normalize, scatter ----------------
// block = 128 threads = 32 rows x 4 channel-groups of 16; grid.x = 8192/32 = 256
__global__ void __launch_bounds__(128) reduce_kernel() {
    int st = blockIdx.y;  // 0 or 1
    int t = threadIdx.x;
    int qi = blockIdx.x * 32 + (t >> 2);
    int cg = t & 3;
    int KS = (st == 0) ? 8 : 2;
    int poff = (st == 0) ? 0 : 8 * 8192;
    int row0 = poff + qi;

    float den = 0.f;
    for (int ksp = 0; ksp < KS; ksp++) den += g_denp[row0 + ksp * 8192];
    float inv = 1.0f / den;

    int shift2 = 13 - 2 * st;
    int Pb = 1 << shift2;
    int b = qi >> shift2, p = qi & (Pb - 1);
    int shift = 6 - st;
    int si = b >> st, sj = b & ((1 << st) - 1);
    int hv = p & 1, tt = p >> 1;
    int hi = tt >> shift, wi = tt & ((1 << shift) - 1);
    int h = (si << shift) + hi;
    int w2 = (sj << shift) + wi + (hv << 6);
    int pos = (h << 7) + w2;

    float* dst = g_ctx + pos * 256 + st * 64 + cg * 16;
#pragma unroll
    for (int c = 0; c < 16; c += 4) {
        float4 s = make_float4(0.f, 0.f, 0.f, 0.f);
        for (int ksp = 0; ksp < KS; ksp++) {
            float4 a = *(const float4*)&g_accp[row0 + ksp * 8192][cg * 16 + c];
            s.x += a.x; s.y += a.y; s.z += a.z; s.w += a.w;
        }
        s.x *= inv; s.y *= inv; s.z *= inv; s.w *= inv;
        *(float4*)(dst + c) = s;
    }
}

// ---------------- 5. final 1x1 conv (64 out x 256 in) + split halves ----------------
__global__ void __launch_bounds__(128) conv_kernel(const float* __restrict__ Wo,
                                                   float* __restrict__ out) {
    __shared__ float ws[64 * 65];
    __shared__ float cs[64 * 65];
    int t = threadIdx.x;
    int pos0 = blockIdx.x * 64;
    int og = t >> 4, pg = t & 15;

    float acc[8][4];
#pragma unroll
    for (int i = 0; i < 8; i++)
#pragma unroll
        for (int j = 0; j < 4; j++) acc[i][j] = 0.f;

    for (int ci0 = 0; ci0 < 256; ci0 += 64) {
        __syncthreads();
        for (int r = 0; r < 32; r++) {
            int idx = r * 128 + t;
            int a = idx >> 6, cc = idx & 63;
            ws[a * 65 + cc] = Wo[a * 256 + ci0 + cc];
            cs[a * 65 + cc] = g_ctx[(pos0 + a) * 256 + ci0 + cc];
        }
        __syncthreads();
#pragma unroll 4
        for (int cc = 0; cc < 64; cc++) {
            float wr[8], xr[4];
#pragma unroll
            for (int i = 0; i < 8; i++) wr[i] = ws[(og * 8 + i) * 65 + cc];
#pragma unroll
            for (int j = 0; j < 4; j++) xr[j] = cs[(pg * 4 + j) * 65 + cc];
#pragma unroll
            for (int i = 0; i < 8; i++)
#pragma unroll
                for (int j = 0; j < 4; j++) acc[i][j] += wr[i] * xr[j];
        }
    }

#pragma unroll
    for (int i = 0; i < 8; i++) {
        int o = og * 8 + i;
#pragma unroll
        for (int j = 0; j < 4; j++) {
            int pos = pos0 + pg * 4 + j;
            int h = pos >> 7, w2 = pos & 127;
            int idx = (w2 < 64) ? (o * 4096 + h * 64 + w2)
                                : (262144 + o * 4096 + h * 64 + (w2 - 64));
            out[idx] = acc[i][j];
        }
    }
}

// ---------------- launch ----------------
extern "C" void kernel_launch(void* const* d_in, const int* in_sizes, int n_in,
                              void* d_out, int out_size) {
    const float* x1 = (const float*)d_in[0];
    const float* x2 = (const float*)d_in[1];
    const float* Wq = (const float*)d_in[2];
    const float* bq = (const float*)d_in[3];
    const float* gq = (const float*)d_in[4];
    const float* beq = (const float*)d_in[5];
    const float* Wk = (const float*)d_in[6];
    const float* bk = (const float*)d_in[7];
    const float* gk = (const float*)d_in[8];
    const float* bek = (const float*)d_in[9];
    const float* Wv = (const float*)d_in[10];
    const float* bv = (const float*)d_in[11];
    const float* Wo = (const float*)d_in[12];
    float* out = (float*)d_out;

    fold_kernel<<<4, 80>>>(Wq, bq, gq, beq, Wk, bk, gk, bek, Wv, bv);
    proj_kernel<<<64, 128>>>(x1, x2);
    flash_kernel<<<768, 128>>>();
    reduce_kernel<<<dim3(256, 2), 128>>>();
    conv_kernel<<<128, 128>>>(Wo, out);
}

// round 5
// speedup vs baseline: 1.7379x; 1.0357x over previous
#include <cuda_runtime.h>
#include <cstdint>

typedef unsigned long long ull;

// ---------------- static scratch (no allocations allowed) ----------------
__device__ float g_Wf[4][80][64];          // folded weights: [stage][o<8:q,8..15:k,16..79:v][c]
__device__ float g_bf[4][80];              // folded biases
__device__ float g_q[4][8 * 8192];         // [st][ b*(8*P) + c*P + p ]   (channel-major, pre-scaled)
__device__ float g_k[4][8 * 8192];         // same layout
__device__ float g_v[4][8192 * 64];        // [st][ (b*P+p)*64 + c ]      (point-major)
__device__ float g_accp[10 * 8192][64];    // split-K partial numerators (stages 0,1 only)
__device__ float g_denp[10 * 8192];        // split-K partial denominators
__device__ float g_ctx[8192 * 256];        // [pos][st*64+c]

// ---------------- f32x2 helpers ----------------
__device__ __forceinline__ ull fma2(ull a, ull b, ull c) {
    ull d;
    asm("fma.rn.f32x2 %0, %1, %2, %3;" : "=l"(d) : "l"(a), "l"(b), "l"(c));
    return d;
}
__device__ __forceinline__ ull pack2(float x, float y) {
    ull d;
    asm("mov.b64 %0, {%1, %2};" : "=l"(d) : "f"(x), "f"(y));
    return d;
}
__device__ __forceinline__ float2 unpack2(ull a) {
    float2 f;
    asm("mov.b64 {%0, %1}, %2;" : "=f"(f.x), "=f"(f.y) : "l"(a));
    return f;
}
__device__ __forceinline__ float ex2(float x) {
    float y;
    asm("ex2.approx.f32 %0, %1;" : "=f"(y) : "f"(x));
    return y;
}

// ---------------- 1. fold BN affine + softmax scale into weights ----------------
__global__ void fold_kernel(const float* __restrict__ Wq, const float* __restrict__ bq,
                            const float* __restrict__ gq, const float* __restrict__ beq,
                            const float* __restrict__ Wk, const float* __restrict__ bk,
                            const float* __restrict__ gk, const float* __restrict__ bek,
                            const float* __restrict__ Wv, const float* __restrict__ bv) {
    int st = blockIdx.x, o = threadIdx.x;
    // kc^-0.5 * log2(e): fold softmax scale + exp2 conversion into q
    const float SCALE = 0.35355339059327373f * 1.4426950408889634f;
    if (o < 8) {
        float g = gq[st * 8 + o];
        for (int c = 0; c < 64; c++)
            g_Wf[st][o][c] = g * Wq[(st * 8 + o) * 64 + c] * SCALE;
        g_bf[st][o] = (g * bq[st * 8 + o] + beq[st * 8 + o]) * SCALE;
    } else if (o < 16) {
        int i = o - 8;
        float g = gk[st * 8 + i];
        for (int c = 0; c < 64; c++)
            g_Wf[st][o][c] = g * Wk[(st * 8 + i) * 64 + c];
        g_bf[st][o] = g * bk[st * 8 + i] + bek[st * 8 + i];
    } else {
        int i = o - 16;
        for (int c = 0; c < 64; c++)
            g_Wf[st][o][c] = Wv[(st * 64 + i) * 64 + c];
        g_bf[st][o] = bv[st * 64 + i];
    }
}

// ---------------- 2. projections: one stage per CTA (grid 64 x 4) ----------------
__global__ void __launch_bounds__(128) proj_kernel(const float* __restrict__ x1,
                                                   const float* __restrict__ x2) {
    __shared__ __align__(16) float sW[80][64];
    __shared__ float sb[80];
    int t = threadIdx.x;
    int st = blockIdx.y;

    // stage weights into smem (5120 floats = 1280 float4)
    {
        const float4* src = (const float4*)g_Wf[st];
        float4* dst = (float4*)sW;
#pragma unroll
        for (int i = 0; i < 10; i++) dst[i * 128 + t] = src[i * 128 + t];
        if (t < 80) sb[t] = g_bf[st][t];
    }
    __syncthreads();

    int pos = blockIdx.x * 128 + t;
    int h = pos >> 7, w2 = pos & 127;
    int w = w2 & 63, hv = w2 >> 6;  // hv = which image half
    const float* xsrc = hv ? x2 : x1;

    float4 xreg[16];
#pragma unroll
    for (int c = 0; c < 16; c++) {
        float4 v;
        v.x = xsrc[(4 * c + 0) * 4096 + h * 64 + w];
        v.y = xsrc[(4 * c + 1) * 4096 + h * 64 + w];
        v.z = xsrc[(4 * c + 2) * 4096 + h * 64 + w];
        v.w = xsrc[(4 * c + 3) * 4096 + h * 64 + w];
        xreg[c] = v;
    }

    int shift = 6 - st;
    int P = 8192 >> (2 * st);
    int m = (1 << shift) - 1;
    int si = h >> shift, hi = h & m;
    int sj = w >> shift, wi = w & m;
    int b = (si << st) + sj;
    int p = (((hi << shift) + wi) << 1) | hv;

    float* qdst = g_q[st] + b * (8 * P);
    float* kdst = g_k[st] + b * (8 * P);
#pragma unroll
    for (int o = 0; o < 8; o++) {
        float aq = sb[o], ak = sb[8 + o];
#pragma unroll
        for (int c = 0; c < 16; c++) {
            float4 xv = xreg[c];
            float4 wq = *(const float4*)&sW[o][4 * c];
            float4 wk = *(const float4*)&sW[8 + o][4 * c];
            aq += wq.x * xv.x + wq.y * xv.y + wq.z * xv.z + wq.w * xv.w;
            ak += wk.x * xv.x + wk.y * xv.y + wk.z * xv.z + wk.w * xv.w;
        }
        qdst[o * P + p] = aq;
        kdst[o * P + p] = ak;
    }
    float* vdst = g_v[st] + (b * P + p) * 64;
#pragma unroll 4
    for (int o = 0; o < 64; o += 4) {
        float a0 = sb[16 + o], a1 = sb[17 + o], a2 = sb[18 + o], a3 = sb[19 + o];
#pragma unroll
        for (int c = 0; c < 16; c++) {
            float4 xv = xreg[c];
            float4 w0 = *(const float4*)&sW[16 + o][4 * c];
            float4 w1 = *(const float4*)&sW[17 + o][4 * c];
            float4 w2v = *(const float4*)&sW[18 + o][4 * c];
            float4 w3 = *(const float4*)&sW[19 + o][4 * c];
            a0 += w0.x * xv.x + w0.y * xv.y + w0.z * xv.z + w0.w * xv.w;
            a1 += w1.x * xv.x + w1.y * xv.y + w1.z * xv.z + w1.w * xv.w;
            a2 += w2v.x * xv.x + w2v.y * xv.y + w2v.z * xv.z + w2v.w * xv.w;
            a3 += w3.x * xv.x + w3.y * xv.y + w3.z * xv.z + w3.w * xv.w;
        }
        float4 a;
        a.x = a0; a.y = a1; a.z = a2; a.w = a3;
        *(float4*)(vdst + o) = a;
    }
}

// ---------------- 3. flash attention: smem-staged E GEMM ----------------
// grid = 768 CTAs: st0: 512 (qt64 x ks8), st1: 128 (b4 x qt16 x ks2), st2: 64, st3: 64
// 128 threads; per CTA: 128 queries. Per 32-key tile:
//   phase1: thread t computes exp-scores for query t, writes duplicated (e,e) pairs to Es
//   phase2: 8q x 8c register-tiled GEMM  acc += Es * V
__global__ void __launch_bounds__(128, 4) flash_kernel() {
    int bid = blockIdx.x, t = threadIdx.x;
    int st, local, KS, poff;
    if (bid < 512)      { st = 0; local = bid;       KS = 8; poff = 0; }
    else if (bid < 640) { st = 1; local = bid - 512; KS = 2; poff = 8 * 8192; }
    else if (bid < 704) { st = 2; local = bid - 640; KS = 1; poff = 0; }
    else                { st = 3; local = bid - 704; KS = 1; poff = 0; }
    int P = 8192 >> (2 * st);
    int QT = P >> 7;               // query tiles per block
    int ks = local % KS; local /= KS;
    int qt = local % QT;
    int b = local / QT;
    int Klen = P / KS;
    int k0 = ks * Klen;

    const float* qbase = g_q[st] + b * (8 * P);
    const float* kbase = g_k[st] + b * (8 * P);
    const float* vbase = g_v[st] + (b * P) * 64;

    int q = qt * 128 + t;       // this thread's query (phase 1)
    int qg = t >> 3, cg = t & 7;  // phase-2 tile coords: queries qg*8..+7, channels cg*8..+7

    ull q2[8];
#pragma unroll
    for (int c = 0; c < 8; c++) {
        float a = qbase[c * P + q];
        q2[c] = pack2(a, a);
    }
    ull acc[8][4];
#pragma unroll
    for (int i = 0; i < 8; i++)
#pragma unroll
        for (int j = 0; j < 4; j++) acc[i][j] = 0ull;
    float den = 0.f;

    __shared__ __align__(16) float Ks[8][32];
    __shared__ __align__(16) float Vs[32][64];
    __shared__ __align__(16) ull Es[32][128];
    __shared__ float den_s[128];

    for (int kt = 0; kt < Klen; kt += 32) {
        __syncthreads();
        // load K tile: 8 x 32 floats = 64 float4 (threads 0..63)
        if (t < 64) {
            int c = t >> 3;
            int j = (t & 7) * 4;
            *(float4*)&Ks[c][j] = *(const float4*)&kbase[c * P + k0 + kt + j];
        }
        // load V tile: 32 x 64 floats = 512 float4
        {
            const float4* src = (const float4*)(vbase + (k0 + kt) * 64);
            float4* dst = (float4*)Vs;
#pragma unroll
            for (int i = 0; i < 4; i++) dst[t + i * 128] = src[t + i * 128];
        }
        __syncthreads();

        // phase 1: scores for query t vs 32 keys, write duplicated exp pairs
#pragma unroll
        for (int j = 0; j < 32; j += 4) {
            ull d01 = 0ull, d23 = 0ull;
#pragma unroll
            for (int c = 0; c < 8; c++) {
                ulonglong2 kf = *(const ulonglong2*)&Ks[c][j];
                d01 = fma2(q2[c], kf.x, d01);
                d23 = fma2(q2[c], kf.y, d23);
            }
            float2 s01 = unpack2(d01), s23 = unpack2(d23);
            float e0 = ex2(s01.x), e1 = ex2(s01.y), e2v = ex2(s23.x), e3 = ex2(s23.y);
            den += (e0 + e1) + (e2v + e3);
            Es[j + 0][t] = pack2(e0, e0);
            Es[j + 1][t] = pack2(e1, e1);
            Es[j + 2][t] = pack2(e2v, e2v);
            Es[j + 3][t] = pack2(e3, e3);
        }
        __syncthreads();

        // phase 2: acc[8q][8c] += E * V over 32 keys
#pragma unroll 2
        for (int k = 0; k < 32; k++) {
            ulonglong2 v01 = *(const ulonglong2*)&Vs[k][cg * 8];
            ulonglong2 v23 = *(const ulonglong2*)&Vs[k][cg * 8 + 4];
#pragma unroll
            for (int qp = 0; qp < 4; qp++) {
                ulonglong2 e2 = *(const ulonglong2*)&Es[k][qg * 8 + qp * 2];
                acc[qp * 2][0] = fma2(e2.x, v01.x, acc[qp * 2][0]);
                acc[qp * 2][1] = fma2(e2.x, v01.y, acc[qp * 2][1]);
                acc[qp * 2][2] = fma2(e2.x, v23.x, acc[qp * 2][2]);
                acc[qp * 2][3] = fma2(e2.x, v23.y, acc[qp * 2][3]);
                acc[qp * 2 + 1][0] = fma2(e2.y, v01.x, acc[qp * 2 + 1][0]);
                acc[qp * 2 + 1][1] = fma2(e2.y, v01.y, acc[qp * 2 + 1][1]);
                acc[qp * 2 + 1][2] = fma2(e2.y, v23.x, acc[qp * 2 + 1][2]);
                acc[qp * 2 + 1][3] = fma2(e2.y, v23.y, acc[qp * 2 + 1][3]);
            }
        }
    }

    den_s[t] = den;
    if (KS > 1) g_denp[poff + ks * 8192 + b * P + q] = den;
    __syncthreads();

    if (KS > 1) {
        // write raw partial numerators; reduce kernel normalizes
#pragma unroll
        for (int i = 0; i < 8; i++) {
            int qq = qt * 128 + qg * 8 + i;
            int row = poff + ks * 8192 + b * P + qq;
            float2 a0 = unpack2(acc[i][0]), a1 = unpack2(acc[i][1]);
            float2 a2 = unpack2(acc[i][2]), a3 = unpack2(acc[i][3]);
            float4 v0; v0.x = a0.x; v0.y = a0.y; v0.z = a1.x; v0.w = a1.y;
            float4 v1; v1.x = a2.x; v1.y = a2.y; v1.z = a3.x; v1.w = a3.y;
            *(float4*)&g_accp[row][cg * 8] = v0;
            *(float4*)&g_accp[row][cg * 8 + 4] = v1;
        }
    } else {
        // complete: normalize and scatter straight to g_ctx
        int shift = 6 - st;
        int si = b >> st, sj = b & ((1 << st) - 1);
#pragma unroll
        for (int i = 0; i < 8; i++) {
            int p = qt * 128 + qg * 8 + i;
            float inv = 1.0f / den_s[qg * 8 + i];
            int hv = p & 1, tt2 = p >> 1;
            int hi = tt2 >> shift, wi = tt2 & ((1 << shift) - 1);
            int h = (si << shift) + hi;
            int w2 = (sj << shift) + wi + (hv << 6);
            int pos = (h << 7) + w2;
            float* dst = g_ctx + pos * 256 + st * 64 + cg * 8;
            float2 a0 = unpack2(acc[i][0]), a1 = unpack2(acc[i][1]);
            float2 a2 = unpack2(acc[i][2]), a3 = unpack2(acc[i][3]);
            float4 v0; v0.x = a0.x * inv; v0.y = a0.y * inv; v0.z = a1.x * inv; v0.w = a1.y * inv;
            float4 v1; v1.x = a2.x * inv; v1.y = a2.y * inv; v1.z = a3.x * inv; v1.w = a3.y * inv;
            *(float4*)(dst) = v0;
            *(float4*)(dst + 4) = v1;
        }
    }
}

// ---------------- 4. reduce splits (stages 0,1), normalize, scatter ----------------
// block = 128 threads = 32 rows x 4 channel-groups of 16; grid.x = 8192/32 = 256
__global__ void __launch_bounds__(128) reduce_kernel() {
    int st = blockIdx.y;  // 0 or 1
    int t = threadIdx.x;
    int qi = blockIdx.x * 32 + (t >> 2);
    int cg = t & 3;
    int KS = (st == 0) ? 8 : 2;
    int poff = (st == 0) ? 0 : 8 * 8192;
    int row0 = poff + qi;

    float den = 0.f;
    for (int ksp = 0; ksp < KS; ksp++) den += g_denp[row0 + ksp * 8192];
    float inv = 1.0f / den;

    int shift2 = 13 - 2 * st;
    int Pb = 1 << shift2;
    int b = qi >> shift2, p = qi & (Pb - 1);
    int shift = 6 - st;
    int si = b >> st, sj = b & ((1 << st) - 1);
    int hv = p & 1, tt = p >> 1;
    int hi = tt >> shift, wi = tt & ((1 << shift) - 1);
    int h = (si << shift) + hi;
    int w2 = (sj << shift) + wi + (hv << 6);
    int pos = (h << 7) + w2;

    float* dst = g_ctx + pos * 256 + st * 64 + cg * 16;
#pragma unroll
    for (int c = 0; c < 16; c += 4) {
        float4 s = make_float4(0.f, 0.f, 0.f, 0.f);
        for (int ksp = 0; ksp < KS; ksp++) {
            float4 a = *(const float4*)&g_accp[row0 + ksp * 8192][cg * 16 + c];
            s.x += a.x; s.y += a.y; s.z += a.z; s.w += a.w;
        }
        s.x *= inv; s.y *= inv; s.z *= inv; s.w *= inv;
        *(float4*)(dst + c) = s;
    }
}

// ---------------- 5. final 1x1 conv (64 out x 256 in) + split halves ----------------
__global__ void __launch_bounds__(128) conv_kernel(const float* __restrict__ Wo,
                                                   float* __restrict__ out) {
    __shared__ float ws[64 * 65];
    __shared__ float cs[64 * 65];
    int t = threadIdx.x;
    int pos0 = blockIdx.x * 64;
    int og = t >> 4, pg = t & 15;

    float acc[8][4];
#pragma unroll
    for (int i = 0; i < 8; i++)
#pragma unroll
        for (int j = 0; j < 4; j++) acc[i][j] = 0.f;

    for (int ci0 = 0; ci0 < 256; ci0 += 64) {
        __syncthreads();
        for (int r = 0; r < 32; r++) {
            int idx = r * 128 + t;
            int a = idx >> 6, cc = idx & 63;
            ws[a * 65 + cc] = Wo[a * 256 + ci0 + cc];
            cs[a * 65 + cc] = g_ctx[(pos0 + a) * 256 + ci0 + cc];
        }
        __syncthreads();
#pragma unroll 4
        for (int cc = 0; cc < 64; cc++) {
            float wr[8], xr[4];
#pragma unroll
            for (int i = 0; i < 8; i++) wr[i] = ws[(og * 8 + i) * 65 + cc];
#pragma unroll
            for (int j = 0; j < 4; j++) xr[j] = cs[(pg * 4 + j) * 65 + cc];
#pragma unroll
            for (int i = 0; i < 8; i++)
#pragma unroll
                for (int j = 0; j < 4; j++) acc[i][j] += wr[i] * xr[j];
        }
    }

#pragma unroll
    for (int i = 0; i < 8; i++) {
        int o = og * 8 + i;
#pragma unroll
        for (int j = 0; j < 4; j++) {
            int pos = pos0 + pg * 4 + j;
            int h = pos >> 7, w2 = pos & 127;
            int idx = (w2 < 64) ? (o * 4096 + h * 64 + w2)
                                : (262144 + o * 4096 + h * 64 + (w2 - 64));
            out[idx] = acc[i][j];
        }
    }
}

// ---------------- launch ----------------
extern "C" void kernel_launch(void* const* d_in, const int* in_sizes, int n_in,
                              void* d_out, int out_size) {
    const float* x1 = (const float*)d_in[0];
    const float* x2 = (const float*)d_in[1];
    const float* Wq = (const float*)d_in[2];
    const float* bq = (const float*)d_in[3];
    const float* gq = (const float*)d_in[4];
    const float* beq = (const float*)d_in[5];
    const float* Wk = (const float*)d_in[6];
    const float* bk = (const float*)d_in[7];
    const float* gk = (const float*)d_in[8];
    const float* bek = (const float*)d_in[9];
    const float* Wv = (const float*)d_in[10];
    const float* bv = (const float*)d_in[11];
    const float* Wo = (const float*)d_in[12];
    float* out = (float*)d_out;

    fold_kernel<<<4, 80>>>(Wq, bq, gq, beq, Wk, bk, gk, bek, Wv, bv);
    proj_kernel<<<dim3(64, 4), 128>>>(x1, x2);
    flash_kernel<<<768, 128>>>();
    reduce_kernel<<<dim3(256, 2), 128>>>();
    conv_kernel<<<128, 128>>>(Wo, out);
}

// round 7
// speedup vs baseline: 3.9097x; 2.2497x over previous
#include <cuda_runtime.h>
#include <cstdint>

typedef unsigned long long ull;

// ---------------- static scratch (no allocations allowed) ----------------
__device__ float g_Wf[4][80][64];          // folded weights: [stage][o<8:q,8..15:k,16..79:v][c]
__device__ float g_bf[4][80];              // folded biases
__device__ float g_q[4][8 * 8192];         // [st][ b*(8*P) + c*P + p ]   channel-major, pre-scaled
__device__ float g_k[4][8 * 8192];         // same layout
__device__ float g_v[4][64 * 8192];        // [st][ b*64*P + c*P + p ]    CHANNEL-major per block
__device__ float g_accp[10 * 8192][64];    // split-K partial numerators (stages 0,1 only)
__device__ float g_denp[10 * 8192];        // split-K partial denominators
__device__ float g_ctx[8192 * 256];        // [pos][st*64+c]

// ---------------- helpers ----------------
__device__ __forceinline__ ull fma2(ull a, ull b, ull c) {
    ull d;
    asm("fma.rn.f32x2 %0, %1, %2, %3;" : "=l"(d) : "l"(a), "l"(b), "l"(c));
    return d;
}
__device__ __forceinline__ ull pack2(float x, float y) {
    ull d;
    asm("mov.b64 %0, {%1, %2};" : "=l"(d) : "f"(x), "f"(y));
    return d;
}
__device__ __forceinline__ float2 unpack2(ull a) {
    float2 f;
    asm("mov.b64 {%0, %1}, %2;" : "=f"(f.x), "=f"(f.y) : "l"(a));
    return f;
}
__device__ __forceinline__ float ex2(float x) {
    float y;
    asm("ex2.approx.f32 %0, %1;" : "=f"(y) : "f"(x));
    return y;
}
__device__ __forceinline__ float tf32r(float x) {  // round-to-nearest tf32 (unbiased)
    uint32_t u;
    asm("cvt.rna.tf32.f32 %0, %1;" : "=r"(u) : "f"(x));
    return __uint_as_float(u);
}

// warp-level tensor-core MMA: D(16x8) += A(16x8,row) * B(8x8,col), tf32 inputs
__device__ __forceinline__ void mma16n8k8(float* d, const uint32_t* a, uint32_t b0, uint32_t b1) {
    asm volatile(
        "mma.sync.aligned.m16n8k8.row.col.f32.tf32.tf32.f32 "
        "{%0,%1,%2,%3}, {%4,%5,%6,%7}, {%8,%9}, {%0,%1,%2,%3};"
        : "+f"(d[0]), "+f"(d[1]), "+f"(d[2]), "+f"(d[3])
        : "r"(a[0]), "r"(a[1]), "r"(a[2]), "r"(a[3]), "r"(b0), "r"(b1));
}

// ---------------- 1. fold BN affine + softmax scale into weights ----------------
__global__ void fold_kernel(const float* __restrict__ Wq, const float* __restrict__ bq,
                            const float* __restrict__ gq, const float* __restrict__ beq,
                            const float* __restrict__ Wk, const float* __restrict__ bk,
                            const float* __restrict__ gk, const float* __restrict__ bek,
                            const float* __restrict__ Wv, const float* __restrict__ bv) {
    int st = blockIdx.x, o = threadIdx.x;
    const float SCALE = 0.35355339059327373f * 1.4426950408889634f;  // kc^-0.5 * log2e
    if (o < 8) {
        float g = gq[st * 8 + o];
        for (int c = 0; c < 64; c++)
            g_Wf[st][o][c] = g * Wq[(st * 8 + o) * 64 + c] * SCALE;
        g_bf[st][o] = (g * bq[st * 8 + o] + beq[st * 8 + o]) * SCALE;
    } else if (o < 16) {
        int i = o - 8;
        float g = gk[st * 8 + i];
        for (int c = 0; c < 64; c++)
            g_Wf[st][o][c] = g * Wk[(st * 8 + i) * 64 + c];
        g_bf[st][o] = g * bk[st * 8 + i] + bek[st * 8 + i];
    } else {
        int i = o - 16;
        for (int c = 0; c < 64; c++)
            g_Wf[st][o][c] = Wv[(st * 64 + i) * 64 + c];
        g_bf[st][o] = bv[st * 64 + i];
    }
}

// ---------------- 2. projections: one stage per CTA (grid 64 x 4) ----------------
__global__ void __launch_bounds__(128) proj_kernel(const float* __restrict__ x1,
                                                   const float* __restrict__ x2) {
    __shared__ __align__(16) float sW[80][64];
    __shared__ float sb[80];
    int t = threadIdx.x;
    int st = blockIdx.y;

    {
        const float4* src = (const float4*)g_Wf[st];
        float4* dst = (float4*)sW;
#pragma unroll
        for (int i = 0; i < 10; i++) dst[i * 128 + t] = src[i * 128 + t];
        if (t < 80) sb[t] = g_bf[st][t];
    }
    __syncthreads();

    int pos = blockIdx.x * 128 + t;
    int h = pos >> 7, w2 = pos & 127;
    int w = w2 & 63, hv = w2 >> 6;
    const float* xsrc = hv ? x2 : x1;

    float4 xreg[16];
#pragma unroll
    for (int c = 0; c < 16; c++) {
        float4 v;
        v.x = xsrc[(4 * c + 0) * 4096 + h * 64 + w];
        v.y = xsrc[(4 * c + 1) * 4096 + h * 64 + w];
        v.z = xsrc[(4 * c + 2) * 4096 + h * 64 + w];
        v.w = xsrc[(4 * c + 3) * 4096 + h * 64 + w];
        xreg[c] = v;
    }

    int shift = 6 - st;
    int P = 8192 >> (2 * st);
    int m = (1 << shift) - 1;
    int si = h >> shift, hi = h & m;
    int sj = w >> shift, wi = w & m;
    int b = (si << st) + sj;
    int p = (((hi << shift) + wi) << 1) | hv;

    float* qdst = g_q[st] + b * (8 * P);
    float* kdst = g_k[st] + b * (8 * P);
#pragma unroll
    for (int o = 0; o < 8; o++) {
        float aq = sb[o], ak = sb[8 + o];
#pragma unroll
        for (int c = 0; c < 16; c++) {
            float4 xv = xreg[c];
            float4 wq = *(const float4*)&sW[o][4 * c];
            float4 wk = *(const float4*)&sW[8 + o][4 * c];
            aq += wq.x * xv.x + wq.y * xv.y + wq.z * xv.z + wq.w * xv.w;
            ak += wk.x * xv.x + wk.y * xv.y + wk.z * xv.z + wk.w * xv.w;
        }
        qdst[o * P + p] = aq;
        kdst[o * P + p] = ak;
    }
    // V: channel-major per block
    float* vdst = g_v[st] + b * (64 * P) + p;
#pragma unroll 4
    for (int o = 0; o < 64; o += 4) {
        float a0 = sb[16 + o], a1 = sb[17 + o], a2 = sb[18 + o], a3 = sb[19 + o];
#pragma unroll
        for (int c = 0; c < 16; c++) {
            float4 xv = xreg[c];
            float4 w0 = *(const float4*)&sW[16 + o][4 * c];
            float4 w1 = *(const float4*)&sW[17 + o][4 * c];
            float4 w2v = *(const float4*)&sW[18 + o][4 * c];
            float4 w3 = *(const float4*)&sW[19 + o][4 * c];
            a0 += w0.x * xv.x + w0.y * xv.y + w0.z * xv.z + w0.w * xv.w;
            a1 += w1.x * xv.x + w1.y * xv.y + w1.z * xv.z + w1.w * xv.w;
            a2 += w2v.x * xv.x + w2v.y * xv.y + w2v.z * xv.z + w2v.w * xv.w;
            a3 += w3.x * xv.x + w3.y * xv.y + w3.z * xv.z + w3.w * xv.w;
        }
        vdst[(o + 0) * P] = a0;
        vdst[(o + 1) * P] = a1;
        vdst[(o + 2) * P] = a2;
        vdst[(o + 3) * P] = a3;
    }
}

// ---------------- 3. flash attention: SIMT scores + mma.sync tf32 EV GEMM ----------------
// grid = 768 CTAs: st0: 512 (qt64 x ks8), st1: 128 (b4 x qt16 x ks2), st2: 64, st3: 64
// Per 32-key tile:
//   phase1: thread t computes exp-scores (tf32-rounded) for query t -> Es[q][k]
//   phase2: per-warp HMMA: 32q x 64c, 2 mtiles x 8 ntiles x 4 ksteps of m16n8k8
__global__ void __launch_bounds__(128, 3) flash_kernel() {
    __shared__ float Es[128][36];   // E [q][k], pitch 36 floats
    __shared__ float Vs[64][36];    // V [c][k], pitch 36
    __shared__ __align__(16) float Ks[8][32];
    __shared__ float den_s[128];

    int bid = blockIdx.x, t = threadIdx.x;
    int st, local, KS, poff;
    if (bid < 512)      { st = 0; local = bid;       KS = 8; poff = 0; }
    else if (bid < 640) { st = 1; local = bid - 512; KS = 2; poff = 8 * 8192; }
    else if (bid < 704) { st = 2; local = bid - 640; KS = 1; poff = 0; }
    else                { st = 3; local = bid - 704; KS = 1; poff = 0; }
    int P = 8192 >> (2 * st);
    int QT = P >> 7;
    int ks = local % KS; local /= KS;
    int qt = local % QT;
    int b = local / QT;
    int Klen = P / KS;
    int k0 = ks * Klen;

    const float* qbase = g_q[st] + b * (8 * P);
    const float* kbase = g_k[st] + b * (8 * P);
    const float* vbase = g_v[st] + b * (64 * P);

    int q = qt * 128 + t;
    int w = t >> 5, lane = t & 31;
    int g = lane >> 2, r = lane & 3;

    ull q2[8];
#pragma unroll
    for (int c = 0; c < 8; c++) {
        float a = qbase[c * P + q];
        q2[c] = pack2(a, a);
    }
    float acc[2][8][4];
#pragma unroll
    for (int mt = 0; mt < 2; mt++)
#pragma unroll
        for (int nt = 0; nt < 8; nt++)
#pragma unroll
            for (int i = 0; i < 4; i++) acc[mt][nt][i] = 0.f;
    float den = 0.f;

    for (int kt = 0; kt < Klen; kt += 32) {
        __syncthreads();  // protect Es/Vs from previous phase 2
        // stage K tile (8 x 32 f32) — threads 0..63
        if (t < 64) {
            int c = t >> 3, j = (t & 7) * 4;
            *(float4*)&Ks[c][j] = *(const float4*)&kbase[c * P + k0 + kt + j];
        }
        // stage V tile (64c x 32k) tf32-rounded
#pragma unroll
        for (int i = 0; i < 4; i++) {
            int idx = t + i * 128;       // 512 16B-chunks
            int c = idx >> 3, j8 = idx & 7;
            float4 v = *(const float4*)&vbase[c * P + k0 + kt + j8 * 4];
            float4 u;
            u.x = tf32r(v.x); u.y = tf32r(v.y); u.z = tf32r(v.z); u.w = tf32r(v.w);
            *(float4*)&Vs[c][j8 * 4] = u;
        }
        __syncthreads();

        // phase 1: scores for query t vs 32 keys -> exp -> tf32 -> Es[t][*]
#pragma unroll
        for (int j = 0; j < 32; j += 4) {
            ull d01 = 0ull, d23 = 0ull;
#pragma unroll
            for (int c = 0; c < 8; c++) {
                ulonglong2 kf = *(const ulonglong2*)&Ks[c][j];
                d01 = fma2(q2[c], kf.x, d01);
                d23 = fma2(q2[c], kf.y, d23);
            }
            float2 s01 = unpack2(d01), s23 = unpack2(d23);
            float e0 = ex2(s01.x), e1 = ex2(s01.y), e2v = ex2(s23.x), e3 = ex2(s23.y);
            den += (e0 + e1) + (e2v + e3);
            float4 u;
            u.x = tf32r(e0); u.y = tf32r(e1); u.z = tf32r(e2v); u.w = tf32r(e3);
            *(float4*)&Es[t][j] = u;
        }
        __syncthreads();

        // phase 2: warp w handles queries w*32..+31, all 64 channels
#pragma unroll
        for (int ks8 = 0; ks8 < 4; ks8++) {
            int kk = ks8 * 8;
            uint32_t afr[2][4];
#pragma unroll
            for (int mt = 0; mt < 2; mt++) {
                int row = w * 32 + mt * 16;
                afr[mt][0] = __float_as_uint(Es[row + g][kk + r]);
                afr[mt][1] = __float_as_uint(Es[row + g + 8][kk + r]);
                afr[mt][2] = __float_as_uint(Es[row + g][kk + r + 4]);
                afr[mt][3] = __float_as_uint(Es[row + g + 8][kk + r + 4]);
            }
#pragma unroll
            for (int nt = 0; nt < 8; nt++) {
                uint32_t b0 = __float_as_uint(Vs[nt * 8 + g][kk + r]);
                uint32_t b1 = __float_as_uint(Vs[nt * 8 + g][kk + r + 4]);
                mma16n8k8(acc[0][nt], afr[0], b0, b1);
                mma16n8k8(acc[1][nt], afr[1], b0, b1);
            }
        }
    }

    den_s[t] = den;
    if (KS > 1) g_denp[poff + ks * 8192 + b * P + q] = den;
    __syncthreads();

    // epilogue: C fragment (mt): rows w*32+mt*16+g (+8), cols nt*8+2r (+1)
    if (KS > 1) {
#pragma unroll
        for (int mt = 0; mt < 2; mt++)
#pragma unroll
            for (int rr = 0; rr < 2; rr++) {
                int qrow = w * 32 + mt * 16 + g + rr * 8;
                int row = poff + ks * 8192 + b * P + qt * 128 + qrow;
#pragma unroll
                for (int nt = 0; nt < 8; nt++) {
                    float2 v;
                    v.x = acc[mt][nt][2 * rr];
                    v.y = acc[mt][nt][2 * rr + 1];
                    *(float2*)&g_accp[row][nt * 8 + 2 * r] = v;
                }
            }
    } else {
        int shift = 6 - st;
        int si = b >> st, sj = b & ((1 << st) - 1);
#pragma unroll
        for (int mt = 0; mt < 2; mt++)
#pragma unroll
            for (int rr = 0; rr < 2; rr++) {
                int qrow = w * 32 + mt * 16 + g + rr * 8;
                int p = qt * 128 + qrow;
                float inv = 1.0f / den_s[qrow];
                int hv = p & 1, tt2 = p >> 1;
                int hi = tt2 >> shift, wi = tt2 & ((1 << shift) - 1);
                int h = (si << shift) + hi;
                int w2 = (sj << shift) + wi + (hv << 6);
                int pos = (h << 7) + w2;
                float* dstp = g_ctx + pos * 256 + st * 64;
#pragma unroll
                for (int nt = 0; nt < 8; nt++) {
                    float2 v;
                    v.x = acc[mt][nt][2 * rr] * inv;
                    v.y = acc[mt][nt][2 * rr + 1] * inv;
                    *(float2*)(dstp + nt * 8 + 2 * r) = v;
                }
            }
    }
}

// ---------------- 4. reduce splits (stages 0,1), normalize, scatter ----------------
__global__ void __launch_bounds__(128) reduce_kernel() {
    int st = blockIdx.y;  // 0 or 1
    int t = threadIdx.x;
    int qi = blockIdx.x * 32 + (t >> 2);
    int cg = t & 3;
    int KS = (st == 0) ? 8 : 2;
    int poff = (st == 0) ? 0 : 8 * 8192;
    int row0 = poff + qi;

    float den = 0.f;
    for (int ksp = 0; ksp < KS; ksp++) den += g_denp[row0 + ksp * 8192];
    float inv = 1.0f / den;

    int shift2 = 13 - 2 * st;
    int Pb = 1 << shift2;
    int b = qi >> shift2, p = qi & (Pb - 1);
    int shift = 6 - st;
    int si = b >> st, sj = b & ((1 << st) - 1);
    int hv = p & 1, tt = p >> 1;
    int hi = tt >> shift, wi = tt & ((1 << shift) - 1);
    int h = (si << shift) + hi;
    int w2 = (sj << shift) + wi + (hv << 6);
    int pos = (h << 7) + w2;

    float* dst = g_ctx + pos * 256 + st * 64 + cg * 16;
#pragma unroll
    for (int c = 0; c < 16; c += 4) {
        float4 s = make_float4(0.f, 0.f, 0.f, 0.f);
        for (int ksp = 0; ksp < KS; ksp++) {
            float4 a = *(const float4*)&g_accp[row0 + ksp * 8192][cg * 16 + c];
            s.x += a.x; s.y += a.y; s.z += a.z; s.w += a.w;
        }
        s.x *= inv; s.y *= inv; s.z *= inv; s.w *= inv;
        *(float4*)(dst + c) = s;
    }
}

// ---------------- 5. final 1x1 conv (64 out x 256 in) + split halves ----------------
__global__ void __launch_bounds__(128) conv_kernel(const float* __restrict__ Wo,
                                                   float* __restrict__ out) {
    __shared__ float ws[64 * 65];
    __shared__ float cs[64 * 65];
    int t = threadIdx.x;
    int pos0 = blockIdx.x * 64;
    int og = t >> 4, pg = t & 15;

    float acc[8][4];
#pragma unroll
    for (int i = 0; i < 8; i++)
#pragma unroll
        for (int j = 0; j < 4; j++) acc[i][j] = 0.f;

    for (int ci0 = 0; ci0 < 256; ci0 += 64) {
        __syncthreads();
        for (int r = 0; r < 32; r++) {
            int idx = r * 128 + t;
            int a = idx >> 6, cc = idx & 63;
            ws[a * 65 + cc] = Wo[a * 256 + ci0 + cc];
            cs[a * 65 + cc] = g_ctx[(pos0 + a) * 256 + ci0 + cc];
        }
        __syncthreads();
#pragma unroll 4
        for (int cc = 0; cc < 64; cc++) {
            float wr[8], xr[4];
#pragma unroll
            for (int i = 0; i < 8; i++) wr[i] = ws[(og * 8 + i) * 65 + cc];
#pragma unroll
            for (int j = 0; j < 4; j++) xr[j] = cs[(pg * 4 + j) * 65 + cc];
#pragma unroll
            for (int i = 0; i < 8; i++)
#pragma unroll
                for (int j = 0; j < 4; j++) acc[i][j] += wr[i] * xr[j];
        }
    }

#pragma unroll
    for (int i = 0; i < 8; i++) {
        int o = og * 8 + i;
#pragma unroll
        for (int j = 0; j < 4; j++) {
            int pos = pos0 + pg * 4 + j;
            int h = pos >> 7, w2 = pos & 127;
            int idx = (w2 < 64) ? (o * 4096 + h * 64 + w2)
                                : (262144 + o * 4096 + h * 64 + (w2 - 64));
            out[idx] = acc[i][j];
        }
    }
}

// ---------------- launch ----------------
extern "C" void kernel_launch(void* const* d_in, const int* in_sizes, int n_in,
                              void* d_out, int out_size) {
    const float* x1 = (const float*)d_in[0];
    const float* x2 = (const float*)d_in[1];
    const float* Wq = (const float*)d_in[2];
    const float* bq = (const float*)d_in[3];
    const float* gq = (const float*)d_in[4];
    const float* beq = (const float*)d_in[5];
    const float* Wk = (const float*)d_in[6];
    const float* bk = (const float*)d_in[7];
    const float* gk = (const float*)d_in[8];
    const float* bek = (const float*)d_in[9];
    const float* Wv = (const float*)d_in[10];
    const float* bv = (const float*)d_in[11];
    const float* Wo = (const float*)d_in[12];
    float* out = (float*)d_out;

    fold_kernel<<<4, 80>>>(Wq, bq, gq, beq, Wk, bk, gk, bek, Wv, bv);
    proj_kernel<<<dim3(64, 4), 128>>>(x1, x2);
    flash_kernel<<<768, 128>>>();
    reduce_kernel<<<dim3(256, 2), 128>>>();
    conv_kernel<<<128, 128>>>(Wo, out);
}

// round 9
// speedup vs baseline: 4.5589x; 1.1660x over previous
#include <cuda_runtime.h>
#include <cstdint>

typedef unsigned long long ull;

// ---------------- static scratch (no allocations allowed) ----------------
__device__ float g_Wf[4][80][64];          // folded weights: [stage][o<8:q,8..15:k,16..79:v][c]
__device__ float g_bf[4][80];              // folded biases
__device__ float g_q[4][8 * 8192];         // [st][ b*8P + c*P + p ]  channel-major, scaled, tf32-rounded
__device__ float g_k[4][8 * 8192];         // [st][ b*8P + p*8 + c ]  KEY-major, tf32-rounded
__device__ float g_v[4][64 * 8192];        // [st][ b*64P + c*P + p ] channel-major, tf32-rounded
__device__ float g_accp[10 * 8192][64];    // split-K partial numerators (stages 0,1 only)
__device__ float g_denp[10 * 8192];        // split-K partial denominators
__device__ float g_ctx[8192 * 256];        // [pos][st*64+c]

// ---------------- helpers ----------------
__device__ __forceinline__ float ex2(float x) {
    float y;
    asm("ex2.approx.f32 %0, %1;" : "=f"(y) : "f"(x));
    return y;
}
__device__ __forceinline__ float tf32r(float x) {  // round-to-nearest tf32 (unbiased)
    uint32_t u;
    asm("cvt.rna.tf32.f32 %0, %1;" : "=r"(u) : "f"(x));
    return __uint_as_float(u);
}

// warp-level tensor-core MMA: D(16x8) += A(16x8,row) * B(8x8,col), tf32 inputs
__device__ __forceinline__ void mma16n8k8(float* d, const uint32_t* a, uint32_t b0, uint32_t b1) {
    asm volatile(
        "mma.sync.aligned.m16n8k8.row.col.f32.tf32.tf32.f32 "
        "{%0,%1,%2,%3}, {%4,%5,%6,%7}, {%8,%9}, {%0,%1,%2,%3};"
        : "+f"(d[0]), "+f"(d[1]), "+f"(d[2]), "+f"(d[3])
        : "r"(a[0]), "r"(a[1]), "r"(a[2]), "r"(a[3]), "r"(b0), "r"(b1));
}

// ---------------- 1. fold BN affine + softmax scale into weights ----------------
__global__ void fold_kernel(const float* __restrict__ Wq, const float* __restrict__ bq,
                            const float* __restrict__ gq, const float* __restrict__ beq,
                            const float* __restrict__ Wk, const float* __restrict__ bk,
                            const float* __restrict__ gk, const float* __restrict__ bek,
                            const float* __restrict__ Wv, const float* __restrict__ bv) {
    int st = blockIdx.x, o = threadIdx.x;
    const float SCALE = 0.35355339059327373f * 1.4426950408889634f;  // kc^-0.5 * log2e
    if (o < 8) {
        float g = gq[st * 8 + o];
        for (int c = 0; c < 64; c++)
            g_Wf[st][o][c] = g * Wq[(st * 8 + o) * 64 + c] * SCALE;
        g_bf[st][o] = (g * bq[st * 8 + o] + beq[st * 8 + o]) * SCALE;
    } else if (o < 16) {
        int i = o - 8;
        float g = gk[st * 8 + i];
        for (int c = 0; c < 64; c++)
            g_Wf[st][o][c] = g * Wk[(st * 8 + i) * 64 + c];
        g_bf[st][o] = g * bk[st * 8 + i] + bek[st * 8 + i];
    } else {
        int i = o - 16;
        for (int c = 0; c < 64; c++)
            g_Wf[st][o][c] = Wv[(st * 64 + i) * 64 + c];
        g_bf[st][o] = bv[st * 64 + i];
    }
}

// ---------------- 2. projections: one stage per CTA (grid 64 x 4), tf32-rounded outputs --------
__global__ void __launch_bounds__(128) proj_kernel(const float* __restrict__ x1,
                                                   const float* __restrict__ x2) {
    __shared__ __align__(16) float sW[80][64];
    __shared__ float sb[80];
    int t = threadIdx.x;
    int st = blockIdx.y;

    {
        const float4* src = (const float4*)g_Wf[st];
        float4* dst = (float4*)sW;
#pragma unroll
        for (int i = 0; i < 10; i++) dst[i * 128 + t] = src[i * 128 + t];
        if (t < 80) sb[t] = g_bf[st][t];
    }
    __syncthreads();

    int pos = blockIdx.x * 128 + t;
    int h = pos >> 7, w2 = pos & 127;
    int w = w2 & 63, hv = w2 >> 6;
    const float* xsrc = hv ? x2 : x1;

    float4 xreg[16];
#pragma unroll
    for (int c = 0; c < 16; c++) {
        float4 v;
        v.x = xsrc[(4 * c + 0) * 4096 + h * 64 + w];
        v.y = xsrc[(4 * c + 1) * 4096 + h * 64 + w];
        v.z = xsrc[(4 * c + 2) * 4096 + h * 64 + w];
        v.w = xsrc[(4 * c + 3) * 4096 + h * 64 + w];
        xreg[c] = v;
    }

    int shift = 6 - st;
    int P = 8192 >> (2 * st);
    int m = (1 << shift) - 1;
    int si = h >> shift, hi = h & m;
    int sj = w >> shift, wi = w & m;
    int b = (si << st) + sj;
    int p = (((hi << shift) + wi) << 1) | hv;

    float* qdst = g_q[st] + b * (8 * P);
    float* kdst = g_k[st] + b * (8 * P);
#pragma unroll
    for (int o = 0; o < 8; o++) {
        float aq = sb[o], ak = sb[8 + o];
#pragma unroll
        for (int c = 0; c < 16; c++) {
            float4 xv = xreg[c];
            float4 wq = *(const float4*)&sW[o][4 * c];
            float4 wk = *(const float4*)&sW[8 + o][4 * c];
            aq += wq.x * xv.x + wq.y * xv.y + wq.z * xv.z + wq.w * xv.w;
            ak += wk.x * xv.x + wk.y * xv.y + wk.z * xv.z + wk.w * xv.w;
        }
        qdst[o * P + p] = tf32r(aq);
        kdst[p * 8 + o] = tf32r(ak);    // key-major
    }
    float* vdst = g_v[st] + b * (64 * P) + p;
#pragma unroll 4
    for (int o = 0; o < 64; o += 4) {
        float a0 = sb[16 + o], a1 = sb[17 + o], a2 = sb[18 + o], a3 = sb[19 + o];
#pragma unroll
        for (int c = 0; c < 16; c++) {
            float4 xv = xreg[c];
            float4 w0 = *(const float4*)&sW[16 + o][4 * c];
            float4 w1 = *(const float4*)&sW[17 + o][4 * c];
            float4 w2v = *(const float4*)&sW[18 + o][4 * c];
            float4 w3 = *(const float4*)&sW[19 + o][4 * c];
            a0 += w0.x * xv.x + w0.y * xv.y + w0.z * xv.z + w0.w * xv.w;
            a1 += w1.x * xv.x + w1.y * xv.y + w1.z * xv.z + w1.w * xv.w;
            a2 += w2v.x * xv.x + w2v.y * xv.y + w2v.z * xv.z + w2v.w * xv.w;
            a3 += w3.x * xv.x + w3.y * xv.y + w3.z * xv.z + w3.w * xv.w;
        }
        vdst[(o + 0) * P] = tf32r(a0);
        vdst[(o + 1) * P] = tf32r(a1);
        vdst[(o + 2) * P] = tf32r(a2);
        vdst[(o + 3) * P] = tf32r(a3);
    }
}

// ---------------- 3. flash attention: full tensor-core (QK + EV both mma.sync tf32) ----------
// grid = 768 CTAs: st0: 512 (qt64 x ks8), st1: 128 (b4 x qt16 x ks2), st2: 64, st3: 64
// Double-buffered K/V tiles; 2 barriers per 32-key tile.
__global__ void __launch_bounds__(128, 4) flash_kernel() {
    __shared__ float Es[128][36];      // exp(scores), tf32-rounded, [q][k]
    __shared__ float Vs[2][64][36];    // V tile [c][k]
    __shared__ float Kt[2][32][36];    // K tile [k][c]

    int bid = blockIdx.x, t = threadIdx.x;
    int st, local, KS, poff;
    if (bid < 512)      { st = 0; local = bid;       KS = 8; poff = 0; }
    else if (bid < 640) { st = 1; local = bid - 512; KS = 2; poff = 8 * 8192; }
    else if (bid < 704) { st = 2; local = bid - 640; KS = 1; poff = 0; }
    else                { st = 3; local = bid - 704; KS = 1; poff = 0; }
    int P = 8192 >> (2 * st);
    int QT = P >> 7;
    int ks = local % KS; local /= KS;
    int qt = local % QT;
    int b = local / QT;
    int Klen = P / KS;
    int k0 = ks * Klen;

    const float* qbase = g_q[st] + b * (8 * P);
    const float* kbase = g_k[st] + b * (8 * P);
    const float* vbase = g_v[st] + b * (64 * P);

    int w = t >> 5, lane = t & 31;
    int g = lane >> 2, r = lane & 3;

    // persistent Q A-fragments: rows qt*128 + w*32 + mt*16 + {g, g+8}, cols (channels) {r, r+4}
    uint32_t qf[2][4];
#pragma unroll
    for (int mt = 0; mt < 2; mt++) {
        int row = qt * 128 + w * 32 + mt * 16;
        qf[mt][0] = __float_as_uint(qbase[r * P + row + g]);
        qf[mt][1] = __float_as_uint(qbase[r * P + row + g + 8]);
        qf[mt][2] = __float_as_uint(qbase[(r + 4) * P + row + g]);
        qf[mt][3] = __float_as_uint(qbase[(r + 4) * P + row + g + 8]);
    }

    float acc[2][8][4];
#pragma unroll
    for (int mt = 0; mt < 2; mt++)
#pragma unroll
        for (int nt = 0; nt < 8; nt++)
#pragma unroll
            for (int i = 0; i < 4; i++) acc[mt][nt][i] = 0.f;
    float den4[2][2] = {{0.f, 0.f}, {0.f, 0.f}};  // [mt][rr]: rows g+rr*8 per mtile

    // stage K (key-major) + V (channel-major) tiles
    auto stage = [&](int kt, int bi) {
        if (kt < Klen) {
            if (t < 64) {
                int key = t >> 1, half = t & 1;
                float4 kv = *(const float4*)&kbase[(k0 + kt + key) * 8 + half * 4];
                *(float4*)&Kt[bi][key][half * 4] = kv;
            }
#pragma unroll
            for (int i = 0; i < 4; i++) {
                int idx = t + i * 128;
                int c = idx >> 3, j8 = idx & 7;
                float4 v = *(const float4*)&vbase[c * P + k0 + kt + j8 * 4];
                *(float4*)&Vs[bi][c][j8 * 4] = v;
            }
        }
    };

    stage(0, 0);
    __syncthreads();

    int nb = Klen >> 5;
    for (int n = 0; n < nb; n++) {
        int cur = n & 1, nxt = cur ^ 1;
        // prefetch next tile (writes buffers phase2(n-1) is done with)
        stage((n + 1) << 5, nxt);

        // phase 1: QK scores via MMA, exp, store Es (each warp: its 32 queries x 32 keys)
#pragma unroll
        for (int nt = 0; nt < 4; nt++) {
            uint32_t kb0 = __float_as_uint(Kt[cur][nt * 8 + g][r]);
            uint32_t kb1 = __float_as_uint(Kt[cur][nt * 8 + g][r + 4]);
            float sc0[4] = {0.f, 0.f, 0.f, 0.f};
            float sc1[4] = {0.f, 0.f, 0.f, 0.f};
            mma16n8k8(sc0, qf[0], kb0, kb1);
            mma16n8k8(sc1, qf[1], kb0, kb1);
            int col = nt * 8 + 2 * r;
            {
                float e0 = tf32r(ex2(sc0[0])), e1 = tf32r(ex2(sc0[1]));
                float e2v = tf32r(ex2(sc0[2])), e3 = tf32r(ex2(sc0[3]));
                den4[0][0] += e0 + e1;
                den4[0][1] += e2v + e3;
                int row = w * 32 + g;
                *(float2*)&Es[row][col] = make_float2(e0, e1);
                *(float2*)&Es[row + 8][col] = make_float2(e2v, e3);
            }
            {
                float e0 = tf32r(ex2(sc1[0])), e1 = tf32r(ex2(sc1[1]));
                float e2v = tf32r(ex2(sc1[2])), e3 = tf32r(ex2(sc1[3]));
                den4[1][0] += e0 + e1;
                den4[1][1] += e2v + e3;
                int row = w * 32 + 16 + g;
                *(float2*)&Es[row][col] = make_float2(e0, e1);
                *(float2*)&Es[row + 8][col] = make_float2(e2v, e3);
            }
        }
        __syncthreads();

        // phase 2: EV GEMM (warp: 32q x 64c)
#pragma unroll
        for (int ks8 = 0; ks8 < 4; ks8++) {
            int kk = ks8 * 8;
            uint32_t afr[2][4];
#pragma unroll
            for (int mt = 0; mt < 2; mt++) {
                int row = w * 32 + mt * 16;
                afr[mt][0] = __float_as_uint(Es[row + g][kk + r]);
                afr[mt][1] = __float_as_uint(Es[row + g + 8][kk + r]);
                afr[mt][2] = __float_as_uint(Es[row + g][kk + r + 4]);
                afr[mt][3] = __float_as_uint(Es[row + g + 8][kk + r + 4]);
            }
#pragma unroll
            for (int nt = 0; nt < 8; nt++) {
                uint32_t b0 = __float_as_uint(Vs[cur][nt * 8 + g][kk + r]);
                uint32_t b1 = __float_as_uint(Vs[cur][nt * 8 + g][kk + r + 4]);
                mma16n8k8(acc[0][nt], afr[0], b0, b1);
                mma16n8k8(acc[1][nt], afr[1], b0, b1);
            }
        }
        __syncthreads();
    }

    // reduce den across the 4 lanes sharing a row (lanes g*4+r, r=0..3)
#pragma unroll
    for (int mt = 0; mt < 2; mt++)
#pragma unroll
        for (int rr = 0; rr < 2; rr++) {
            float d = den4[mt][rr];
            d += __shfl_xor_sync(0xFFFFFFFFu, d, 1);
            d += __shfl_xor_sync(0xFFFFFFFFu, d, 2);
            den4[mt][rr] = d;
        }

    if (KS > 1) {
#pragma unroll
        for (int mt = 0; mt < 2; mt++)
#pragma unroll
            for (int rr = 0; rr < 2; rr++) {
                int qrow = w * 32 + mt * 16 + g + rr * 8;
                int row = poff + ks * 8192 + b * P + qt * 128 + qrow;
                if (r == 0) g_denp[row] = den4[mt][rr];
#pragma unroll
                for (int nt = 0; nt < 8; nt++) {
                    float2 v;
                    v.x = acc[mt][nt][2 * rr];
                    v.y = acc[mt][nt][2 * rr + 1];
                    *(float2*)&g_accp[row][nt * 8 + 2 * r] = v;
                }
            }
    } else {
        int shift = 6 - st;
        int si = b >> st, sj = b & ((1 << st) - 1);
#pragma unroll
        for (int mt = 0; mt < 2; mt++)
#pragma unroll
            for (int rr = 0; rr < 2; rr++) {
                int qrow = w * 32 + mt * 16 + g + rr * 8;
                int p = qt * 128 + qrow;
                float inv = 1.0f / den4[mt][rr];
                int hv = p & 1, tt2 = p >> 1;
                int hi = tt2 >> shift, wi = tt2 & ((1 << shift) - 1);
                int h = (si << shift) + hi;
                int w2 = (sj << shift) + wi + (hv << 6);
                int pos = (h << 7) + w2;
                float* dstp = g_ctx + pos * 256 + st * 64;
#pragma unroll
                for (int nt = 0; nt < 8; nt++) {
                    float2 v;
                    v.x = acc[mt][nt][2 * rr] * inv;
                    v.y = acc[mt][nt][2 * rr + 1] * inv;
                    *(float2*)(dstp + nt * 8 + 2 * r) = v;
                }
            }
    }
}

// ---------------- 4. reduce splits (stages 0,1), normalize, scatter ----------------
__global__ void __launch_bounds__(128) reduce_kernel() {
    int st = blockIdx.y;  // 0 or 1
    int t = threadIdx.x;
    int qi = blockIdx.x * 32 + (t >> 2);
    int cg = t & 3;
    int KS = (st == 0) ? 8 : 2;
    int poff = (st == 0) ? 0 : 8 * 8192;
    int row0 = poff + qi;

    float den = 0.f;
    for (int ksp = 0; ksp < KS; ksp++) den += g_denp[row0 + ksp * 8192];
    float inv = 1.0f / den;

    int shift2 = 13 - 2 * st;
    int Pb = 1 << shift2;
    int b = qi >> shift2, p = qi & (Pb - 1);
    int shift = 6 - st;
    int si = b >> st, sj = b & ((1 << st) - 1);
    int hv = p & 1, tt = p >> 1;
    int hi = tt >> shift, wi = tt & ((1 << shift) - 1);
    int h = (si << shift) + hi;
    int w2 = (sj << shift) + wi + (hv << 6);
    int pos = (h << 7) + w2;

    float* dst = g_ctx + pos * 256 + st * 64 + cg * 16;
#pragma unroll
    for (int c = 0; c < 16; c += 4) {
        float4 s = make_float4(0.f, 0.f, 0.f, 0.f);
        for (int ksp = 0; ksp < KS; ksp++) {
            float4 a = *(const float4*)&g_accp[row0 + ksp * 8192][cg * 16 + c];
            s.x += a.x; s.y += a.y; s.z += a.z; s.w += a.w;
        }
        s.x *= inv; s.y *= inv; s.z *= inv; s.w *= inv;
        *(float4*)(dst + c) = s;
    }
}

// ---------------- 5. final 1x1 conv (64 out x 256 in) + split halves ----------------
__global__ void __launch_bounds__(128) conv_kernel(const float* __restrict__ Wo,
                                                   float* __restrict__ out) {
    __shared__ float ws[64 * 65];
    __shared__ float cs[64 * 65];
    int t = threadIdx.x;
    int pos0 = blockIdx.x * 64;
    int og = t >> 4, pg = t & 15;

    float acc[8][4];
#pragma unroll
    for (int i = 0; i < 8; i++)
#pragma unroll
        for (int j = 0; j < 4; j++) acc[i][j] = 0.f;

    for (int ci0 = 0; ci0 < 256; ci0 += 64) {
        __syncthreads();
        for (int r = 0; r < 32; r++) {
            int idx = r * 128 + t;
            int a = idx >> 6, cc = idx & 63;
            ws[a * 65 + cc] = Wo[a * 256 + ci0 + cc];
            cs[a * 65 + cc] = g_ctx[(pos0 + a) * 256 + ci0 + cc];
        }
        __syncthreads();
#pragma unroll 4
        for (int cc = 0; cc < 64; cc++) {
            float wr[8], xr[4];
#pragma unroll
            for (int i = 0; i < 8; i++) wr[i] = ws[(og * 8 + i) * 65 + cc];
#pragma unroll
            for (int j = 0; j < 4; j++) xr[j] = cs[(pg * 4 + j) * 65 + cc];
#pragma unroll
            for (int i = 0; i < 8; i++)
#pragma unroll
                for (int j = 0; j < 4; j++) acc[i][j] += wr[i] * xr[j];
        }
    }

#pragma unroll
    for (int i = 0; i < 8; i++) {
        int o = og * 8 + i;
#pragma unroll
        for (int j = 0; j < 4; j++) {
            int pos = pos0 + pg * 4 + j;
            int h = pos >> 7, w2 = pos & 127;
            int idx = (w2 < 64) ? (o * 4096 + h * 64 + w2)
                                : (262144 + o * 4096 + h * 64 + (w2 - 64));
            out[idx] = acc[i][j];
        }
    }
}

// ---------------- launch ----------------
extern "C" void kernel_launch(void* const* d_in, const int* in_sizes, int n_in,
                              void* d_out, int out_size) {
    const float* x1 = (const float*)d_in[0];
    const float* x2 = (const float*)d_in[1];
    const float* Wq = (const float*)d_in[2];
    const float* bq = (const float*)d_in[3];
    const float* gq = (const float*)d_in[4];
    const float* beq = (const float*)d_in[5];
    const float* Wk = (const float*)d_in[6];
    const float* bk = (const float*)d_in[7];
    const float* gk = (const float*)d_in[8];
    const float* bek = (const float*)d_in[9];
    const float* Wv = (const float*)d_in[10];
    const float* bv = (const float*)d_in[11];
    const float* Wo = (const float*)d_in[12];
    float* out = (float*)d_out;

    fold_kernel<<<4, 80>>>(Wq, bq, gq, beq, Wk, bk, gk, bek, Wv, bv);
    proj_kernel<<<dim3(64, 4), 128>>>(x1, x2);
    flash_kernel<<<768, 128>>>();
    reduce_kernel<<<dim3(256, 2), 128>>>();
    conv_kernel<<<128, 128>>>(Wo, out);
}

// round 11
// speedup vs baseline: 4.6821x; 1.0270x over previous
#include <cuda_runtime.h>
#include <cstdint>

typedef unsigned long long ull;

// ---------------- static scratch (no allocations allowed) ----------------
__device__ float g_Wf[4][80][64];          // folded weights: [stage][o<8:q,8..15:k,16..79:v][c]
__device__ float g_bf[4][80];              // folded biases
__device__ float g_q[4][8 * 8192];         // [st][ b*8P + c*P + p ]  channel-major, scaled, tf32-rounded
__device__ float g_k[4][8 * 8192];         // [st][ b*8P + p*8 + c ]  KEY-major, tf32-rounded
__device__ float g_v[4][64 * 8192];        // [st][ b*64P + c*P + p ] channel-major, tf32-rounded
__device__ float g_accp[10 * 8192][64];    // split-K partial numerators (stages 0,1 only)
__device__ float g_denp[10 * 8192];        // split-K partial denominators
__device__ float g_ctx[8192 * 256];        // [pos][st*64+c]

// ---------------- helpers ----------------
__device__ __forceinline__ float ex2(float x) {
    float y;
    asm("ex2.approx.f32 %0, %1;" : "=f"(y) : "f"(x));
    return y;
}
__device__ __forceinline__ float tf32r(float x) {  // round-to-nearest tf32 (unbiased)
    uint32_t u;
    asm("cvt.rna.tf32.f32 %0, %1;" : "=r"(u) : "f"(x));
    return __uint_as_float(u);
}

// warp-level tensor-core MMA: D(16x8) += A(16x8,row) * B(8x8,col), tf32 inputs
__device__ __forceinline__ void mma16n8k8(float* d, const uint32_t* a, uint32_t b0, uint32_t b1) {
    asm volatile(
        "mma.sync.aligned.m16n8k8.row.col.f32.tf32.tf32.f32 "
        "{%0,%1,%2,%3}, {%4,%5,%6,%7}, {%8,%9}, {%0,%1,%2,%3};"
        : "+f"(d[0]), "+f"(d[1]), "+f"(d[2]), "+f"(d[3])
        : "r"(a[0]), "r"(a[1]), "r"(a[2]), "r"(a[3]), "r"(b0), "r"(b1));
}

// ---------------- 1. fold BN affine + softmax scale into weights ----------------
__global__ void fold_kernel(const float* __restrict__ Wq, const float* __restrict__ bq,
                            const float* __restrict__ gq, const float* __restrict__ beq,
                            const float* __restrict__ Wk, const float* __restrict__ bk,
                            const float* __restrict__ gk, const float* __restrict__ bek,
                            const float* __restrict__ Wv, const float* __restrict__ bv) {
    int st = blockIdx.x, o = threadIdx.x;
    const float SCALE = 0.35355339059327373f * 1.4426950408889634f;  // kc^-0.5 * log2e
    if (o < 8) {
        float g = gq[st * 8 + o];
        for (int c = 0; c < 64; c++)
            g_Wf[st][o][c] = g * Wq[(st * 8 + o) * 64 + c] * SCALE;
        g_bf[st][o] = (g * bq[st * 8 + o] + beq[st * 8 + o]) * SCALE;
    } else if (o < 16) {
        int i = o - 8;
        float g = gk[st * 8 + i];
        for (int c = 0; c < 64; c++)
            g_Wf[st][o][c] = g * Wk[(st * 8 + i) * 64 + c];
        g_bf[st][o] = g * bk[st * 8 + i] + bek[st * 8 + i];
    } else {
        int i = o - 16;
        for (int c = 0; c < 64; c++)
            g_Wf[st][o][c] = Wv[(st * 64 + i) * 64 + c];
        g_bf[st][o] = bv[st * 64 + i];
    }
}

// ---------------- 2. projections: one stage per CTA (grid 64 x 4), tf32-rounded outputs --------
__global__ void __launch_bounds__(128) proj_kernel(const float* __restrict__ x1,
                                                   const float* __restrict__ x2) {
    __shared__ __align__(16) float sW[80][64];
    __shared__ float sb[80];
    int t = threadIdx.x;
    int st = blockIdx.y;

    {
        const float4* src = (const float4*)g_Wf[st];
        float4* dst = (float4*)sW;
#pragma unroll
        for (int i = 0; i < 10; i++) dst[i * 128 + t] = src[i * 128 + t];
        if (t < 80) sb[t] = g_bf[st][t];
    }
    __syncthreads();

    int pos = blockIdx.x * 128 + t;
    int h = pos >> 7, w2 = pos & 127;
    int w = w2 & 63, hv = w2 >> 6;
    const float* xsrc = hv ? x2 : x1;

    float4 xreg[16];
#pragma unroll
    for (int c = 0; c < 16; c++) {
        float4 v;
        v.x = xsrc[(4 * c + 0) * 4096 + h * 64 + w];
        v.y = xsrc[(4 * c + 1) * 4096 + h * 64 + w];
        v.z = xsrc[(4 * c + 2) * 4096 + h * 64 + w];
        v.w = xsrc[(4 * c + 3) * 4096 + h * 64 + w];
        xreg[c] = v;
    }

    int shift = 6 - st;
    int P = 8192 >> (2 * st);
    int m = (1 << shift) - 1;
    int si = h >> shift, hi = h & m;
    int sj = w >> shift, wi = w & m;
    int b = (si << st) + sj;
    int p = (((hi << shift) + wi) << 1) | hv;

    float* qdst = g_q[st] + b * (8 * P);
    float* kdst = g_k[st] + b * (8 * P);
#pragma unroll
    for (int o = 0; o < 8; o++) {
        float aq = sb[o], ak = sb[8 + o];
#pragma unroll
        for (int c = 0; c < 16; c++) {
            float4 xv = xreg[c];
            float4 wq = *(const float4*)&sW[o][4 * c];
            float4 wk = *(const float4*)&sW[8 + o][4 * c];
            aq += wq.x * xv.x + wq.y * xv.y + wq.z * xv.z + wq.w * xv.w;
            ak += wk.x * xv.x + wk.y * xv.y + wk.z * xv.z + wk.w * xv.w;
        }
        qdst[o * P + p] = tf32r(aq);
        kdst[p * 8 + o] = tf32r(ak);    // key-major
    }
    float* vdst = g_v[st] + b * (64 * P) + p;
#pragma unroll 4
    for (int o = 0; o < 64; o += 4) {
        float a0 = sb[16 + o], a1 = sb[17 + o], a2 = sb[18 + o], a3 = sb[19 + o];
#pragma unroll
        for (int c = 0; c < 16; c++) {
            float4 xv = xreg[c];
            float4 w0 = *(const float4*)&sW[16 + o][4 * c];
            float4 w1 = *(const float4*)&sW[17 + o][4 * c];
            float4 w2v = *(const float4*)&sW[18 + o][4 * c];
            float4 w3 = *(const float4*)&sW[19 + o][4 * c];
            a0 += w0.x * xv.x + w0.y * xv.y + w0.z * xv.z + w0.w * xv.w;
            a1 += w1.x * xv.x + w1.y * xv.y + w1.z * xv.z + w1.w * xv.w;
            a2 += w2v.x * xv.x + w2v.y * xv.y + w2v.z * xv.z + w2v.w * xv.w;
            a3 += w3.x * xv.x + w3.y * xv.y + w3.z * xv.z + w3.w * xv.w;
        }
        vdst[(o + 0) * P] = tf32r(a0);
        vdst[(o + 1) * P] = tf32r(a1);
        vdst[(o + 2) * P] = tf32r(a2);
        vdst[(o + 3) * P] = tf32r(a3);
    }
}

// ---------------- 3. flash attention: full tensor-core, ONE barrier per tile ----------
// grid = 768 CTAs: st0: 512 (qt64 x ks8), st1: 128 (b4 x qt16 x ks2), st2: 64, st3: 64
__global__ void __launch_bounds__(128, 4) flash_kernel() {
    __shared__ float Es[128][36];      // exp(scores), tf32-rounded, [q][k] — WARP-PRIVATE rows
    __shared__ float Vs[2][64][36];    // V tile [c][k]
    __shared__ float Kt[2][32][36];    // K tile [k][c]

    int bid = blockIdx.x, t = threadIdx.x;
    int st, local, KS, poff;
    if (bid < 512)      { st = 0; local = bid;       KS = 8; poff = 0; }
    else if (bid < 640) { st = 1; local = bid - 512; KS = 2; poff = 8 * 8192; }
    else if (bid < 704) { st = 2; local = bid - 640; KS = 1; poff = 0; }
    else                { st = 3; local = bid - 704; KS = 1; poff = 0; }
    int P = 8192 >> (2 * st);
    int QT = P >> 7;
    int ks = local % KS; local /= KS;
    int qt = local % QT;
    int b = local / QT;
    int Klen = P / KS;
    int k0 = ks * Klen;

    const float* qbase = g_q[st] + b * (8 * P);
    const float* kbase = g_k[st] + b * (8 * P);
    const float* vbase = g_v[st] + b * (64 * P);

    int w = t >> 5, lane = t & 31;
    int g = lane >> 2, r = lane & 3;

    // persistent Q A-fragments
    uint32_t qf[2][4];
#pragma unroll
    for (int mt = 0; mt < 2; mt++) {
        int row = qt * 128 + w * 32 + mt * 16;
        qf[mt][0] = __float_as_uint(qbase[r * P + row + g]);
        qf[mt][1] = __float_as_uint(qbase[r * P + row + g + 8]);
        qf[mt][2] = __float_as_uint(qbase[(r + 4) * P + row + g]);
        qf[mt][3] = __float_as_uint(qbase[(r + 4) * P + row + g + 8]);
    }

    float acc[2][8][4];
#pragma unroll
    for (int mt = 0; mt < 2; mt++)
#pragma unroll
        for (int nt = 0; nt < 8; nt++)
#pragma unroll
            for (int i = 0; i < 4; i++) acc[mt][nt][i] = 0.f;
    float den4[2][2] = {{0.f, 0.f}, {0.f, 0.f}};

    auto stage = [&](int kt, int bi) {
        if (kt < Klen) {
            if (t < 64) {
                int key = t >> 1, half = t & 1;
                float4 kv = *(const float4*)&kbase[(k0 + kt + key) * 8 + half * 4];
                *(float4*)&Kt[bi][key][half * 4] = kv;
            }
#pragma unroll
            for (int i = 0; i < 4; i++) {
                int idx = t + i * 128;
                int c = idx >> 3, j8 = idx & 7;
                float4 v = *(const float4*)&vbase[c * P + k0 + kt + j8 * 4];
                *(float4*)&Vs[bi][c][j8 * 4] = v;
            }
        }
    };

    stage(0, 0);
    __syncthreads();

    int nb = Klen >> 5;
    for (int n = 0; n < nb; n++) {
        int cur = n & 1, nxt = cur ^ 1;
        // prefetch next tile early: overlaps with both MMA phases.
        // nxt buffers were last read in iteration n-1, protected by its end barrier.
        stage((n + 1) << 5, nxt);

        // phase 1: QK scores via MMA, exp, store Es (warp-private rows)
#pragma unroll
        for (int nt = 0; nt < 4; nt++) {
            uint32_t kb0 = __float_as_uint(Kt[cur][nt * 8 + g][r]);
            uint32_t kb1 = __float_as_uint(Kt[cur][nt * 8 + g][r + 4]);
            float sc0[4] = {0.f, 0.f, 0.f, 0.f};
            float sc1[4] = {0.f, 0.f, 0.f, 0.f};
            mma16n8k8(sc0, qf[0], kb0, kb1);
            mma16n8k8(sc1, qf[1], kb0, kb1);
            int col = nt * 8 + 2 * r;
            {
                float e0 = tf32r(ex2(sc0[0])), e1 = tf32r(ex2(sc0[1]));
                float e2v = tf32r(ex2(sc0[2])), e3 = tf32r(ex2(sc0[3]));
                den4[0][0] += e0 + e1;
                den4[0][1] += e2v + e3;
                int row = w * 32 + g;
                *(float2*)&Es[row][col] = make_float2(e0, e1);
                *(float2*)&Es[row + 8][col] = make_float2(e2v, e3);
            }
            {
                float e0 = tf32r(ex2(sc1[0])), e1 = tf32r(ex2(sc1[1]));
                float e2v = tf32r(ex2(sc1[2])), e3 = tf32r(ex2(sc1[3]));
                den4[1][0] += e0 + e1;
                den4[1][1] += e2v + e3;
                int row = w * 32 + 16 + g;
                *(float2*)&Es[row][col] = make_float2(e0, e1);
                *(float2*)&Es[row + 8][col] = make_float2(e2v, e3);
            }
        }
        __syncwarp();   // Es is warp-private: warp-level visibility suffices

        // phase 2: EV GEMM (warp: 32q x 64c)
#pragma unroll
        for (int ks8 = 0; ks8 < 4; ks8++) {
            int kk = ks8 * 8;
            uint32_t afr[2][4];
#pragma unroll
            for (int mt = 0; mt < 2; mt++) {
                int row = w * 32 + mt * 16;
                afr[mt][0] = __float_as_uint(Es[row + g][kk + r]);
                afr[mt][1] = __float_as_uint(Es[row + g + 8][kk + r]);
                afr[mt][2] = __float_as_uint(Es[row + g][kk + r + 4]);
                afr[mt][3] = __float_as_uint(Es[row + g + 8][kk + r + 4]);
            }
#pragma unroll
            for (int nt = 0; nt < 8; nt++) {
                uint32_t b0 = __float_as_uint(Vs[cur][nt * 8 + g][kk + r]);
                uint32_t b1 = __float_as_uint(Vs[cur][nt * 8 + g][kk + r + 4]);
                mma16n8k8(acc[0][nt], afr[0], b0, b1);
                mma16n8k8(acc[1][nt], afr[1], b0, b1);
            }
        }
        __syncthreads();  // single cross-warp barrier per tile
    }

    // reduce den across the 4 lanes sharing a row
#pragma unroll
    for (int mt = 0; mt < 2; mt++)
#pragma unroll
        for (int rr = 0; rr < 2; rr++) {
            float d = den4[mt][rr];
            d += __shfl_xor_sync(0xFFFFFFFFu, d, 1);
            d += __shfl_xor_sync(0xFFFFFFFFu, d, 2);
            den4[mt][rr] = d;
        }

    if (KS > 1) {
#pragma unroll
        for (int mt = 0; mt < 2; mt++)
#pragma unroll
            for (int rr = 0; rr < 2; rr++) {
                int qrow = w * 32 + mt * 16 + g + rr * 8;
                int row = poff + ks * 8192 + b * P + qt * 128 + qrow;
                if (r == 0) g_denp[row] = den4[mt][rr];
#pragma unroll
                for (int nt = 0; nt < 8; nt++) {
                    float2 v;
                    v.x = acc[mt][nt][2 * rr];
                    v.y = acc[mt][nt][2 * rr + 1];
                    *(float2*)&g_accp[row][nt * 8 + 2 * r] = v;
                }
            }
    } else {
        int shift = 6 - st;
        int si = b >> st, sj = b & ((1 << st) - 1);
#pragma unroll
        for (int mt = 0; mt < 2; mt++)
#pragma unroll
            for (int rr = 0; rr < 2; rr++) {
                int qrow = w * 32 + mt * 16 + g + rr * 8;
                int p = qt * 128 + qrow;
                float inv = 1.0f / den4[mt][rr];
                int hv = p & 1, tt2 = p >> 1;
                int hi = tt2 >> shift, wi = tt2 & ((1 << shift) - 1);
                int h = (si << shift) + hi;
                int w2 = (sj << shift) + wi + (hv << 6);
                int pos = (h << 7) + w2;
                float* dstp = g_ctx + pos * 256 + st * 64;
#pragma unroll
                for (int nt = 0; nt < 8; nt++) {
                    float2 v;
                    v.x = acc[mt][nt][2 * rr] * inv;
                    v.y = acc[mt][nt][2 * rr + 1] * inv;
                    *(float2*)(dstp + nt * 8 + 2 * r) = v;
                }
            }
    }
}

// ---------------- 4. reduce splits (stages 0,1), normalize, scatter ----------------
__global__ void __launch_bounds__(128) reduce_kernel() {
    int st = blockIdx.y;  // 0 or 1
    int t = threadIdx.x;
    int qi = blockIdx.x * 32 + (t >> 2);
    int cg = t & 3;
    int KS = (st == 0) ? 8 : 2;
    int poff = (st == 0) ? 0 : 8 * 8192;
    int row0 = poff + qi;

    float den = 0.f;
    for (int ksp = 0; ksp < KS; ksp++) den += g_denp[row0 + ksp * 8192];
    float inv = 1.0f / den;

    int shift2 = 13 - 2 * st;
    int Pb = 1 << shift2;
    int b = qi >> shift2, p = qi & (Pb - 1);
    int shift = 6 - st;
    int si = b >> st, sj = b & ((1 << st) - 1);
    int hv = p & 1, tt = p >> 1;
    int hi = tt >> shift, wi = tt & ((1 << shift) - 1);
    int h = (si << shift) + hi;
    int w2 = (sj << shift) + wi + (hv << 6);
    int pos = (h << 7) + w2;

    float* dst = g_ctx + pos * 256 + st * 64 + cg * 16;
#pragma unroll
    for (int c = 0; c < 16; c += 4) {
        float4 s = make_float4(0.f, 0.f, 0.f, 0.f);
        for (int ksp = 0; ksp < KS; ksp++) {
            float4 a = *(const float4*)&g_accp[row0 + ksp * 8192][cg * 16 + c];
            s.x += a.x; s.y += a.y; s.z += a.z; s.w += a.w;
        }
        s.x *= inv; s.y *= inv; s.z *= inv; s.w *= inv;
        *(float4*)(dst + c) = s;
    }
}

// ---------------- 5. final 1x1 conv via tf32 MMA: out[64 x 8192] = Wo[64 x 256] * ctx^T ------
// grid = 128 CTAs x 64 positions; warp w: 16 positions (2 ntiles), all 64 outputs (4 mtiles)
__global__ void __launch_bounds__(128) conv_kernel(const float* __restrict__ Wo,
                                                   float* __restrict__ out) {
    __shared__ float As[64][36];   // ctx tile [pos][k]
    __shared__ float Bs[64][36];   // Wo tile  [o][k]
    int t = threadIdx.x;
    int pos0 = blockIdx.x * 64;
    int w = t >> 5, lane = t & 31;
    int g = lane >> 2, r = lane & 3;

    float acc[4][2][4];
#pragma unroll
    for (int mt = 0; mt < 4; mt++)
#pragma unroll
        for (int nt = 0; nt < 2; nt++)
#pragma unroll
            for (int i = 0; i < 4; i++) acc[mt][nt][i] = 0.f;

    for (int ci0 = 0; ci0 < 256; ci0 += 32) {
        __syncthreads();
#pragma unroll
        for (int i = 0; i < 4; i++) {
            int idx = t + i * 128;         // 512 chunks of 16B
            int a = idx >> 3, j8 = idx & 7;
            float4 v = *(const float4*)&g_ctx[(pos0 + a) * 256 + ci0 + j8 * 4];
            v.x = tf32r(v.x); v.y = tf32r(v.y); v.z = tf32r(v.z); v.w = tf32r(v.w);
            *(float4*)&As[a][j8 * 4] = v;
            float4 u = *(const float4*)&Wo[a * 256 + ci0 + j8 * 4];
            u.x = tf32r(u.x); u.y = tf32r(u.y); u.z = tf32r(u.z); u.w = tf32r(u.w);
            *(float4*)&Bs[a][j8 * 4] = u;
        }
        __syncthreads();

#pragma unroll
        for (int ks8 = 0; ks8 < 4; ks8++) {
            int kk = ks8 * 8;
            uint32_t af[4][4];
#pragma unroll
            for (int mt = 0; mt < 4; mt++) {
                int row = mt * 16;
                af[mt][0] = __float_as_uint(Bs[row + g][kk + r]);
                af[mt][1] = __float_as_uint(Bs[row + g + 8][kk + r]);
                af[mt][2] = __float_as_uint(Bs[row + g][kk + r + 4]);
                af[mt][3] = __float_as_uint(Bs[row + g + 8][kk + r + 4]);
            }
#pragma unroll
            for (int nt = 0; nt < 2; nt++) {
                uint32_t b0 = __float_as_uint(As[w * 16 + nt * 8 + g][kk + r]);
                uint32_t b1 = __float_as_uint(As[w * 16 + nt * 8 + g][kk + r + 4]);
#pragma unroll
                for (int mt = 0; mt < 4; mt++) mma16n8k8(acc[mt][nt], af[mt], b0, b1);
            }
        }
    }

    // epilogue: C(m=o, n=pos); pairs of positions are contiguous and never cross half boundary
#pragma unroll
    for (int mt = 0; mt < 4; mt++)
#pragma unroll
        for (int rr = 0; rr < 2; rr++) {
            int o = mt * 16 + g + rr * 8;
#pragma unroll
            for (int nt = 0; nt < 2; nt++) {
                int pos = pos0 + w * 16 + nt * 8 + 2 * r;
                int h = pos >> 7, w2 = pos & 127;
                int idx = (w2 < 64) ? (o * 4096 + h * 64 + w2)
                                    : (262144 + o * 4096 + h * 64 + (w2 - 64));
                float2 v;
                v.x = acc[mt][nt][2 * rr];
                v.y = acc[mt][nt][2 * rr + 1];
                *(float2*)&out[idx] = v;
            }
        }
}

// ---------------- launch ----------------
extern "C" void kernel_launch(void* const* d_in, const int* in_sizes, int n_in,
                              void* d_out, int out_size) {
    const float* x1 = (const float*)d_in[0];
    const float* x2 = (const float*)d_in[1];
    const float* Wq = (const float*)d_in[2];
    const float* bq = (const float*)d_in[3];
    const float* gq = (const float*)d_in[4];
    const float* beq = (const float*)d_in[5];
    const float* Wk = (const float*)d_in[6];
    const float* bk = (const float*)d_in[7];
    const float* gk = (const float*)d_in[8];
    const float* bek = (const float*)d_in[9];
    const float* Wv = (const float*)d_in[10];
    const float* bv = (const float*)d_in[11];
    const float* Wo = (const float*)d_in[12];
    float* out = (float*)d_out;

    fold_kernel<<<4, 80>>>(Wq, bq, gq, beq, Wk, bk, gk, bek, Wv, bv);
    proj_kernel<<<dim3(64, 4), 128>>>(x1, x2);
    flash_kernel<<<768, 128>>>();
    reduce_kernel<<<dim3(256, 2), 128>>>();
    conv_kernel<<<128, 128>>>(Wo, out);
}

// round 13
// speedup vs baseline: 7.0554x; 1.5069x over previous
#include <cuda_runtime.h>
#include <cuda_fp16.h>
#include <cstdint>

typedef unsigned long long ull;

// ---------------- static scratch (no allocations allowed) ----------------
__device__ float g_Wf[4][80][64];          // folded weights: [stage][o<8:q,8..15:k,16..79:v][c]
__device__ float g_bf[4][80];              // folded biases
__device__ __half g_q[4][8 * 8192];        // [st][ b*8P + p*8 + c ]  POINT-major, scaled, f16
__device__ __half g_k[4][8 * 8192];        // [st][ b*8P + p*8 + c ]  point-major, f16
__device__ __half g_v[4][64 * 8192];       // [st][ b*64P + c*P + p ] channel-major, f16
__device__ float g_accp[10 * 8192][64];    // split-K partial numerators (stages 0,1 only)
__device__ float g_denp[10 * 8192];        // split-K partial denominators
__device__ float g_ctx[8192 * 256];        // [pos][st*64+c]

// ---------------- helpers ----------------
__device__ __forceinline__ float ex2(float x) {
    float y;
    asm("ex2.approx.f32 %0, %1;" : "=f"(y) : "f"(x));
    return y;
}
__device__ __forceinline__ float tf32r(float x) {
    uint32_t u;
    asm("cvt.rna.tf32.f32 %0, %1;" : "=r"(u) : "f"(x));
    return __uint_as_float(u);
}
// pack two f32 into f16x2: lo = first elem (smaller k), hi = second
__device__ __forceinline__ uint32_t packh2(float lo, float hi) {
    uint32_t d;
    asm("cvt.rn.f16x2.f32 %0, %1, %2;" : "=r"(d) : "f"(hi), "f"(lo));
    return d;
}

// tf32 MMA (kept for conv): D(16x8) += A(16x8,row) * B(8x8,col)
__device__ __forceinline__ void mma16n8k8(float* d, const uint32_t* a, uint32_t b0, uint32_t b1) {
    asm volatile(
        "mma.sync.aligned.m16n8k8.row.col.f32.tf32.tf32.f32 "
        "{%0,%1,%2,%3}, {%4,%5,%6,%7}, {%8,%9}, {%0,%1,%2,%3};"
        : "+f"(d[0]), "+f"(d[1]), "+f"(d[2]), "+f"(d[3])
        : "r"(a[0]), "r"(a[1]), "r"(a[2]), "r"(a[3]), "r"(b0), "r"(b1));
}
// f16 MMA k=8: D(16x8) += A(16x8,row,f16) * B(8x8,col,f16)
__device__ __forceinline__ void mma_h808(float* d, uint32_t a0, uint32_t a1, uint32_t b0) {
    asm volatile(
        "mma.sync.aligned.m16n8k8.row.col.f32.f16.f16.f32 "
        "{%0,%1,%2,%3}, {%4,%5}, {%6}, {%0,%1,%2,%3};"
        : "+f"(d[0]), "+f"(d[1]), "+f"(d[2]), "+f"(d[3])
        : "r"(a0), "r"(a1), "r"(b0));
}
// f16 MMA k=16: D(16x8) += A(16x16,row,f16) * B(16x8,col,f16)
__device__ __forceinline__ void mma_h16816(float* d, uint32_t a0, uint32_t a1, uint32_t a2,
                                           uint32_t a3, uint32_t b0, uint32_t b1) {
    asm volatile(
        "mma.sync.aligned.m16n8k16.row.col.f32.f16.f16.f32 "
        "{%0,%1,%2,%3}, {%4,%5,%6,%7}, {%8,%9}, {%0,%1,%2,%3};"
        : "+f"(d[0]), "+f"(d[1]), "+f"(d[2]), "+f"(d[3])
        : "r"(a0), "r"(a1), "r"(a2), "r"(a3), "r"(b0), "r"(b1));
}

// ---------------- 1. fold BN affine + softmax scale into weights ----------------
__global__ void fold_kernel(const float* __restrict__ Wq, const float* __restrict__ bq,
                            const float* __restrict__ gq, const float* __restrict__ beq,
                            const float* __restrict__ Wk, const float* __restrict__ bk,
                            const float* __restrict__ gk, const float* __restrict__ bek,
                            const float* __restrict__ Wv, const float* __restrict__ bv) {
    int st = blockIdx.x, o = threadIdx.x;
    const float SCALE = 0.35355339059327373f * 1.4426950408889634f;  // kc^-0.5 * log2e
    if (o < 8) {
        float g = gq[st * 8 + o];
        for (int c = 0; c < 64; c++)
            g_Wf[st][o][c] = g * Wq[(st * 8 + o) * 64 + c] * SCALE;
        g_bf[st][o] = (g * bq[st * 8 + o] + beq[st * 8 + o]) * SCALE;
    } else if (o < 16) {
        int i = o - 8;
        float g = gk[st * 8 + i];
        for (int c = 0; c < 64; c++)
            g_Wf[st][o][c] = g * Wk[(st * 8 + i) * 64 + c];
        g_bf[st][o] = g * bk[st * 8 + i] + bek[st * 8 + i];
    } else {
        int i = o - 16;
        for (int c = 0; c < 64; c++)
            g_Wf[st][o][c] = Wv[(st * 64 + i) * 64 + c];
        g_bf[st][o] = bv[st * 64 + i];
    }
}

// ---------------- 2. projections: one stage per CTA (grid 64 x 4), f16 outputs --------
__global__ void __launch_bounds__(128) proj_kernel(const float* __restrict__ x1,
                                                   const float* __restrict__ x2) {
    __shared__ __align__(16) float sW[80][64];
    __shared__ float sb[80];
    int t = threadIdx.x;
    int st = blockIdx.y;

    {
        const float4* src = (const float4*)g_Wf[st];
        float4* dst = (float4*)sW;
#pragma unroll
        for (int i = 0; i < 10; i++) dst[i * 128 + t] = src[i * 128 + t];
        if (t < 80) sb[t] = g_bf[st][t];
    }
    __syncthreads();

    int pos = blockIdx.x * 128 + t;
    int h = pos >> 7, w2 = pos & 127;
    int w = w2 & 63, hv = w2 >> 6;
    const float* xsrc = hv ? x2 : x1;

    float4 xreg[16];
#pragma unroll
    for (int c = 0; c < 16; c++) {
        float4 v;
        v.x = xsrc[(4 * c + 0) * 4096 + h * 64 + w];
        v.y = xsrc[(4 * c + 1) * 4096 + h * 64 + w];
        v.z = xsrc[(4 * c + 2) * 4096 + h * 64 + w];
        v.w = xsrc[(4 * c + 3) * 4096 + h * 64 + w];
        xreg[c] = v;
    }

    int shift = 6 - st;
    int P = 8192 >> (2 * st);
    int m = (1 << shift) - 1;
    int si = h >> shift, hi = h & m;
    int sj = w >> shift, wi = w & m;
    int b = (si << st) + sj;
    int p = (((hi << shift) + wi) << 1) | hv;

    __half* qdst = g_q[st] + b * (8 * P) + p * 8;
    __half* kdst = g_k[st] + b * (8 * P) + p * 8;
#pragma unroll
    for (int o = 0; o < 8; o++) {
        float aq = sb[o], ak = sb[8 + o];
#pragma unroll
        for (int c = 0; c < 16; c++) {
            float4 xv = xreg[c];
            float4 wq = *(const float4*)&sW[o][4 * c];
            float4 wk = *(const float4*)&sW[8 + o][4 * c];
            aq += wq.x * xv.x + wq.y * xv.y + wq.z * xv.z + wq.w * xv.w;
            ak += wk.x * xv.x + wk.y * xv.y + wk.z * xv.z + wk.w * xv.w;
        }
        qdst[o] = __float2half_rn(aq);
        kdst[o] = __float2half_rn(ak);
    }
    __half* vdst = g_v[st] + b * (64 * P) + p;
#pragma unroll 4
    for (int o = 0; o < 64; o += 4) {
        float a0 = sb[16 + o], a1 = sb[17 + o], a2 = sb[18 + o], a3 = sb[19 + o];
#pragma unroll
        for (int c = 0; c < 16; c++) {
            float4 xv = xreg[c];
            float4 w0 = *(const float4*)&sW[16 + o][4 * c];
            float4 w1 = *(const float4*)&sW[17 + o][4 * c];
            float4 w2v = *(const float4*)&sW[18 + o][4 * c];
            float4 w3 = *(const float4*)&sW[19 + o][4 * c];
            a0 += w0.x * xv.x + w0.y * xv.y + w0.z * xv.z + w0.w * xv.w;
            a1 += w1.x * xv.x + w1.y * xv.y + w1.z * xv.z + w1.w * xv.w;
            a2 += w2v.x * xv.x + w2v.y * xv.y + w2v.z * xv.z + w2v.w * xv.w;
            a3 += w3.x * xv.x + w3.y * xv.y + w3.z * xv.z + w3.w * xv.w;
        }
        vdst[(o + 0) * P] = __float2half_rn(a0);
        vdst[(o + 1) * P] = __float2half_rn(a1);
        vdst[(o + 2) * P] = __float2half_rn(a2);
        vdst[(o + 3) * P] = __float2half_rn(a3);
    }
}

// ---------------- 3. flash attention: full fp16 tensor-core, E stays in registers ----------
// grid = 768 CTAs: st0: 512 (qt64 x ks8), st1: 128 (b4 x qt16 x ks2), st2: 64, st3: 64
__global__ void __launch_bounds__(128, 4) flash_kernel() {
    __shared__ __half Vs[2][64][40];   // V tile [c][k], pitch 40 halves
    __shared__ __half Kt[2][32][8];    // K tile [key][ch]

    int bid = blockIdx.x, t = threadIdx.x;
    int st, local, KS, poff;
    if (bid < 512)      { st = 0; local = bid;       KS = 8; poff = 0; }
    else if (bid < 640) { st = 1; local = bid - 512; KS = 2; poff = 8 * 8192; }
    else if (bid < 704) { st = 2; local = bid - 640; KS = 1; poff = 0; }
    else                { st = 3; local = bid - 704; KS = 1; poff = 0; }
    int P = 8192 >> (2 * st);
    int QT = P >> 7;
    int ks = local % KS; local /= KS;
    int qt = local % QT;
    int b = local / QT;
    int Klen = P / KS;
    int k0 = ks * Klen;

    const __half* qbase = g_q[st] + b * (8 * P);
    const __half* kbase = g_k[st] + b * (8 * P);
    const __half* vbase = g_v[st] + b * (64 * P);

    int w = t >> 5, lane = t & 31;
    int g = lane >> 2, r = lane & 3;

    // persistent Q A-fragments (f16, k=8): a0 = row g halves(2r,2r+1), a1 = row g+8
    uint32_t qf[2][2];
#pragma unroll
    for (int mt = 0; mt < 2; mt++) {
        int row = qt * 128 + w * 32 + mt * 16;
        qf[mt][0] = *(const uint32_t*)&qbase[(row + g) * 8 + 2 * r];
        qf[mt][1] = *(const uint32_t*)&qbase[(row + g + 8) * 8 + 2 * r];
    }

    float acc[2][8][4];
#pragma unroll
    for (int mt = 0; mt < 2; mt++)
#pragma unroll
        for (int nt = 0; nt < 8; nt++)
#pragma unroll
            for (int i = 0; i < 4; i++) acc[mt][nt][i] = 0.f;
    float den4[2][2] = {{0.f, 0.f}, {0.f, 0.f}};

    auto stage = [&](int kt, int bi) {
        if (kt < Klen) {
            if (t < 32) {
                *(float4*)&Kt[bi][t][0] = *(const float4*)&kbase[(k0 + kt + t) * 8];
            }
#pragma unroll
            for (int i = 0; i < 2; i++) {
                int idx = t + i * 128;          // 256 chunks of 8 halves
                int c = idx >> 2, j8 = idx & 3;
                *(float4*)&Vs[bi][c][j8 * 8] =
                    *(const float4*)&vbase[c * P + k0 + kt + j8 * 8];
            }
        }
    };

    stage(0, 0);
    __syncthreads();

    int nb = Klen >> 5;
    for (int n = 0; n < nb; n++) {
        int cur = n & 1, nxt = cur ^ 1;
        stage((n + 1) << 5, nxt);   // overlaps both MMA phases

        // phase 1: QK via f16 MMA -> exp -> pack E as f16x2 A-fragments (registers only)
        uint32_t eh[2][4][2];
#pragma unroll
        for (int nt = 0; nt < 4; nt++) {
            uint32_t kb = *(const uint32_t*)&Kt[cur][nt * 8 + g][2 * r];
            float sc0[4] = {0.f, 0.f, 0.f, 0.f};
            float sc1[4] = {0.f, 0.f, 0.f, 0.f};
            mma_h808(sc0, qf[0][0], qf[0][1], kb);
            mma_h808(sc1, qf[1][0], qf[1][1], kb);
            float e00 = ex2(sc0[0]), e01 = ex2(sc0[1]), e02 = ex2(sc0[2]), e03 = ex2(sc0[3]);
            den4[0][0] += e00 + e01;
            den4[0][1] += e02 + e03;
            eh[0][nt][0] = packh2(e00, e01);
            eh[0][nt][1] = packh2(e02, e03);
            float e10 = ex2(sc1[0]), e11 = ex2(sc1[1]), e12 = ex2(sc1[2]), e13 = ex2(sc1[3]);
            den4[1][0] += e10 + e11;
            den4[1][1] += e12 + e13;
            eh[1][nt][0] = packh2(e10, e11);
            eh[1][nt][1] = packh2(e12, e13);
        }

        // phase 2: EV via f16 m16n8k16; A from registers (eh), B from Vs
#pragma unroll
        for (int k16 = 0; k16 < 2; k16++) {
#pragma unroll
            for (int nt = 0; nt < 8; nt++) {
                uint32_t b0 = *(const uint32_t*)&Vs[cur][nt * 8 + g][16 * k16 + 2 * r];
                uint32_t b1 = *(const uint32_t*)&Vs[cur][nt * 8 + g][16 * k16 + 8 + 2 * r];
                mma_h16816(acc[0][nt], eh[0][2 * k16][0], eh[0][2 * k16][1],
                           eh[0][2 * k16 + 1][0], eh[0][2 * k16 + 1][1], b0, b1);
                mma_h16816(acc[1][nt], eh[1][2 * k16][0], eh[1][2 * k16][1],
                           eh[1][2 * k16 + 1][0], eh[1][2 * k16 + 1][1], b0, b1);
            }
        }
        __syncthreads();   // single barrier per tile
    }

    // reduce den across the 4 lanes sharing a row
#pragma unroll
    for (int mt = 0; mt < 2; mt++)
#pragma unroll
        for (int rr = 0; rr < 2; rr++) {
            float d = den4[mt][rr];
            d += __shfl_xor_sync(0xFFFFFFFFu, d, 1);
            d += __shfl_xor_sync(0xFFFFFFFFu, d, 2);
            den4[mt][rr] = d;
        }

    if (KS > 1) {
#pragma unroll
        for (int mt = 0; mt < 2; mt++)
#pragma unroll
            for (int rr = 0; rr < 2; rr++) {
                int qrow = w * 32 + mt * 16 + g + rr * 8;
                int row = poff + ks * 8192 + b * P + qt * 128 + qrow;
                if (r == 0) g_denp[row] = den4[mt][rr];
#pragma unroll
                for (int nt = 0; nt < 8; nt++) {
                    float2 v;
                    v.x = acc[mt][nt][2 * rr];
                    v.y = acc[mt][nt][2 * rr + 1];
                    *(float2*)&g_accp[row][nt * 8 + 2 * r] = v;
                }
            }
    } else {
        int shift = 6 - st;
        int si = b >> st, sj = b & ((1 << st) - 1);
#pragma unroll
        for (int mt = 0; mt < 2; mt++)
#pragma unroll
            for (int rr = 0; rr < 2; rr++) {
                int qrow = w * 32 + mt * 16 + g + rr * 8;
                int p = qt * 128 + qrow;
                float inv = 1.0f / den4[mt][rr];
                int hv = p & 1, tt2 = p >> 1;
                int hi = tt2 >> shift, wi = tt2 & ((1 << shift) - 1);
                int h = (si << shift) + hi;
                int w2 = (sj << shift) + wi + (hv << 6);
                int pos = (h << 7) + w2;
                float* dstp = g_ctx + pos * 256 + st * 64;
#pragma unroll
                for (int nt = 0; nt < 8; nt++) {
                    float2 v;
                    v.x = acc[mt][nt][2 * rr] * inv;
                    v.y = acc[mt][nt][2 * rr + 1] * inv;
                    *(float2*)(dstp + nt * 8 + 2 * r) = v;
                }
            }
    }
}

// ---------------- 4. reduce splits (stages 0,1), normalize, scatter ----------------
__global__ void __launch_bounds__(128) reduce_kernel() {
    int st = blockIdx.y;  // 0 or 1
    int t = threadIdx.x;
    int qi = blockIdx.x * 32 + (t >> 2);
    int cg = t & 3;
    int KS = (st == 0) ? 8 : 2;
    int poff = (st == 0) ? 0 : 8 * 8192;
    int row0 = poff + qi;

    float den = 0.f;
    for (int ksp = 0; ksp < KS; ksp++) den += g_denp[row0 + ksp * 8192];
    float inv = 1.0f / den;

    int shift2 = 13 - 2 * st;
    int Pb = 1 << shift2;
    int b = qi >> shift2, p = qi & (Pb - 1);
    int shift = 6 - st;
    int si = b >> st, sj = b & ((1 << st) - 1);
    int hv = p & 1, tt = p >> 1;
    int hi = tt >> shift, wi = tt & ((1 << shift) - 1);
    int h = (si << shift) + hi;
    int w2 = (sj << shift) + wi + (hv << 6);
    int pos = (h << 7) + w2;

    float* dst = g_ctx + pos * 256 + st * 64 + cg * 16;
#pragma unroll
    for (int c = 0; c < 16; c += 4) {
        float4 s = make_float4(0.f, 0.f, 0.f, 0.f);
        for (int ksp = 0; ksp < KS; ksp++) {
            float4 a = *(const float4*)&g_accp[row0 + ksp * 8192][cg * 16 + c];
            s.x += a.x; s.y += a.y; s.z += a.z; s.w += a.w;
        }
        s.x *= inv; s.y *= inv; s.z *= inv; s.w *= inv;
        *(float4*)(dst + c) = s;
    }
}

// ---------------- 5. final 1x1 conv via tf32 MMA: out[64 x 8192] = Wo[64 x 256] * ctx^T ------
__global__ void __launch_bounds__(128) conv_kernel(const float* __restrict__ Wo,
                                                   float* __restrict__ out) {
    __shared__ float As[64][36];   // ctx tile [pos][k]
    __shared__ float Bs[64][36];   // Wo tile  [o][k]
    int t = threadIdx.x;
    int pos0 = blockIdx.x * 64;
    int w = t >> 5, lane = t & 31;
    int g = lane >> 2, r = lane & 3;

    float acc[4][2][4];
#pragma unroll
    for (int mt = 0; mt < 4; mt++)
#pragma unroll
        for (int nt = 0; nt < 2; nt++)
#pragma unroll
            for (int i = 0; i < 4; i++) acc[mt][nt][i] = 0.f;

    for (int ci0 = 0; ci0 < 256; ci0 += 32) {
        __syncthreads();
#pragma unroll
        for (int i = 0; i < 4; i++) {
            int idx = t + i * 128;
            int a = idx >> 3, j8 = idx & 7;
            float4 v = *(const float4*)&g_ctx[(pos0 + a) * 256 + ci0 + j8 * 4];
            v.x = tf32r(v.x); v.y = tf32r(v.y); v.z = tf32r(v.z); v.w = tf32r(v.w);
            *(float4*)&As[a][j8 * 4] = v;
            float4 u = *(const float4*)&Wo[a * 256 + ci0 + j8 * 4];
            u.x = tf32r(u.x); u.y = tf32r(u.y); u.z = tf32r(u.z); u.w = tf32r(u.w);
            *(float4*)&Bs[a][j8 * 4] = u;
        }
        __syncthreads();

#pragma unroll
        for (int ks8 = 0; ks8 < 4; ks8++) {
            int kk = ks8 * 8;
            uint32_t af[4][4];
#pragma unroll
            for (int mt = 0; mt < 4; mt++) {
                int row = mt * 16;
                af[mt][0] = __float_as_uint(Bs[row + g][kk + r]);
                af[mt][1] = __float_as_uint(Bs[row + g + 8][kk + r]);
                af[mt][2] = __float_as_uint(Bs[row + g][kk + r + 4]);
                af[mt][3] = __float_as_uint(Bs[row + g + 8][kk + r + 4]);
            }
#pragma unroll
            for (int nt = 0; nt < 2; nt++) {
                uint32_t b0 = __float_as_uint(As[w * 16 + nt * 8 + g][kk + r]);
                uint32_t b1 = __float_as_uint(As[w * 16 + nt * 8 + g][kk + r + 4]);
#pragma unroll
                for (int mt = 0; mt < 4; mt++) mma16n8k8(acc[mt][nt], af[mt], b0, b1);
            }
        }
    }

#pragma unroll
    for (int mt = 0; mt < 4; mt++)
#pragma unroll
        for (int rr = 0; rr < 2; rr++) {
            int o = mt * 16 + g + rr * 8;
#pragma unroll
            for (int nt = 0; nt < 2; nt++) {
                int pos = pos0 + w * 16 + nt * 8 + 2 * r;
                int h = pos >> 7, w2 = pos & 127;
                int idx = (w2 < 64) ? (o * 4096 + h * 64 + w2)
                                    : (262144 + o * 4096 + h * 64 + (w2 - 64));
                float2 v;
                v.x = acc[mt][nt][2 * rr];
                v.y = acc[mt][nt][2 * rr + 1];
                *(float2*)&out[idx] = v;
            }
        }
}

// ---------------- launch ----------------
extern "C" void kernel_launch(void* const* d_in, const int* in_sizes, int n_in,
                              void* d_out, int out_size) {
    const float* x1 = (const float*)d_in[0];
    const float* x2 = (const float*)d_in[1];
    const float* Wq = (const float*)d_in[2];
    const float* bq = (const float*)d_in[3];
    const float* gq = (const float*)d_in[4];
    const float* beq = (const float*)d_in[5];
    const float* Wk = (const float*)d_in[6];
    const float* bk = (const float*)d_in[7];
    const float* gk = (const float*)d_in[8];
    const float* bek = (const float*)d_in[9];
    const float* Wv = (const float*)d_in[10];
    const float* bv = (const float*)d_in[11];
    const float* Wo = (const float*)d_in[12];
    float* out = (float*)d_out;

    fold_kernel<<<4, 80>>>(Wq, bq, gq, beq, Wk, bk, gk, bek, Wv, bv);
    proj_kernel<<<dim3(64, 4), 128>>>(x1, x2);
    flash_kernel<<<768, 128>>>();
    reduce_kernel<<<dim3(256, 2), 128>>>();
    conv_kernel<<<128, 128>>>(Wo, out);
}